// round 3
// baseline (speedup 1.0000x reference)
#include <cuda_runtime.h>
#include <cuda_bf16.h>

#define NN 50000
#define EE 800000
#define DD 64

// ---------------- scratch (static device globals; no allocation) ----------------
__device__ __align__(16) int   g_src[EE];
__device__ __align__(16) int   g_dst[EE];
__device__ __align__(16) float g_alpha[EE];
__device__ __align__(16) float g_hx[NN * DD];
__device__ __align__(16) float g_agg[NN * DD];
__device__ __align__(16) float g_m[NN];
__device__ __align__(16) float g_ssum[NN];
__device__ __align__(16) float g_ssrc[NN];
__device__ __align__(16) float g_sdst[NN];
__device__ int g_is64;

// atomic max for float (all finite values incl. negatives; init -inf)
__device__ __forceinline__ void atomicMaxFloat(float* addr, float value) {
    if (value >= 0.0f) {
        atomicMax((int*)addr, __float_as_int(value));
    } else {
        atomicMin((unsigned int*)addr, __float_as_uint(value));
    }
}

// ---------------- kernels ----------------

// Detect whether edge_index buffer is int64 (as int32: odd positions all 0)
__global__ void k_detect(const int* __restrict__ ei) {
    __shared__ int any_nonzero;
    if (threadIdx.x == 0) any_nonzero = 0;
    __syncthreads();
    for (int i = threadIdx.x; i < 4096; i += blockDim.x) {
        if (ei[2 * i + 1] != 0) any_nonzero = 1;   // benign race
    }
    __syncthreads();
    if (threadIdx.x == 0) g_is64 = (any_nonzero == 0);
}

// edge_index -> int32 src/dst (handles int32 or int64 input layout)
__global__ void k_convert(const int* __restrict__ ei) {
    int e = blockIdx.x * blockDim.x + threadIdx.x;
    if (e < EE) {
        int s, d;
        if (g_is64) {
            s = ei[2 * e];
            d = ei[2 * (EE + e)];
        } else {
            s = ei[e];
            d = ei[EE + e];
        }
        // clamp for safety (never trap; wrongness would surface as rel_err)
        s = min(max(s, 0), NN - 1);
        d = min(max(d, 0), NN - 1);
        g_src[e] = s;
        g_dst[e] = d;
    }
}

// hx = h @ W (+bias, +relu optional); if attn: also s_src/s_dst = (hx*a).sum(-1)
// If out == nullptr, write result rows to g_hx instead.
// blockDim = (64, 4)
__global__ void k_gemm(const float* __restrict__ h, const float* __restrict__ W,
                       const float* __restrict__ bias, int do_relu,
                       const float* __restrict__ a_s, const float* __restrict__ a_d,
                       float* __restrict__ out) {
    __shared__ float sW[64 * 64];
    __shared__ float sh[4][64];
    __shared__ float red_s[4][4];

    const int tx = threadIdx.x;   // column 0..63
    const int ty = threadIdx.y;   // row-in-block 0..3
    const int tid = ty * 64 + tx;

    float* __restrict__ hx = out ? out : g_hx;

    for (int i = tid; i < 64 * 64; i += 256) sW[i] = W[i];
    __syncthreads();

    for (int row0 = blockIdx.x * 4; row0 < NN; row0 += gridDim.x * 4) {
        const int r = row0 + ty;   // NN % 4 == 0 -> uniform validity per block
        if (r < NN) sh[ty][tx] = h[r * 64 + tx];
        __syncthreads();
        if (r < NN) {
            float acc = 0.0f;
            #pragma unroll
            for (int k = 0; k < 64; k++) acc = fmaf(sh[ty][k], sW[k * 64 + tx], acc);
            if (bias) acc += bias[tx];
            if (do_relu) acc = fmaxf(acc, 0.0f);
            hx[r * 64 + tx] = acc;
            if (a_s) {
                float vs = acc * a_s[tx];
                float vd = acc * a_d[tx];
                #pragma unroll
                for (int o = 16; o > 0; o >>= 1) {
                    vs += __shfl_down_sync(0xffffffffu, vs, o);
                    vd += __shfl_down_sync(0xffffffffu, vd, o);
                }
                const int half = tx >> 5;   // two warps per row
                if ((tx & 31) == 0) { red_s[ty][half * 2] = vs; red_s[ty][half * 2 + 1] = vd; }
            }
        }
        __syncthreads();
        if (a_s && (row0 + ty) < NN && tx == 0) {
            g_ssrc[row0 + ty] = red_s[ty][0] + red_s[ty][2];
            g_sdst[row0 + ty] = red_s[ty][1] + red_s[ty][3];
        }
        __syncthreads();
    }
}

// reset m/ssum and zero agg
__global__ void k_init() {
    int i = blockIdx.x * blockDim.x + threadIdx.x;
    if (i < NN * DD) g_agg[i] = 0.0f;
    if (i < NN) {
        g_m[i] = __int_as_float(0xff800000);  // -inf
        g_ssum[i] = 0.0f;
    }
}

// alpha = leaky_relu(s_src[src] + s_dst[dst]); atomic max per dst
__global__ void k_edge_max() {
    int e = blockIdx.x * blockDim.x + threadIdx.x;
    if (e < EE) {
        const int s = g_src[e];
        const int d = g_dst[e];
        float a = g_ssrc[s] + g_sdst[d];
        a = (a >= 0.0f) ? a : 0.2f * a;
        g_alpha[e] = a;
        atomicMaxFloat(&g_m[d], a);
    }
}

// e = exp(alpha - m[dst]); alpha <- e; atomic sum per dst
__global__ void k_edge_sum() {
    int e = blockIdx.x * blockDim.x + threadIdx.x;
    if (e < EE) {
        const int d = g_dst[e];
        float ev = __expf(g_alpha[e] - g_m[d]);
        g_alpha[e] = ev;
        atomicAdd(&g_ssum[d], ev);
    }
}

// agg[dst] += hx[src] * p   (16 threads/edge, 4 floats each)
__global__ void k_scatter() {
    long long t = (long long)blockIdx.x * blockDim.x + threadIdx.x;
    int e = (int)(t >> 4);
    int lane = (int)(t & 15);
    if (e < EE) {
        const int s = g_src[e];
        const int d = g_dst[e];
        const float p = g_alpha[e] / g_ssum[d];
        const float4 v = *(const float4*)(g_hx + s * 64 + lane * 4);
        float* dp = g_agg + d * 64 + lane * 4;
        atomicAdd(dp + 0, v.x * p);
        atomicAdd(dp + 1, v.y * p);
        atomicAdd(dp + 2, v.z * p);
        atomicAdd(dp + 3, v.w * p);
    }
}

// out += relu(agg + bias)
__global__ void k_finalize(float* __restrict__ out, const float* __restrict__ bias) {
    int i = blockIdx.x * blockDim.x + threadIdx.x;
    if (i < NN * DD) {
        const int c = i & 63;
        float v = g_agg[i] + bias[c];
        out[i] += fmaxf(v, 0.0f);
    }
}

// ---------------- launch ----------------
extern "C" void kernel_launch(void* const* d_in, const int* in_sizes, int n_in,
                              void* d_out, int out_size) {
    const float* x   = (const float*)d_in[0];
    const int*   ei  = (const int*)d_in[1];   // int32 (JAX x64 disabled) or int64 (detected)
    // d_in[2] edge_weight, d_in[3] edge_attr: unused
    const float* W0  = (const float*)d_in[4];
    const float* b0  = (const float*)d_in[5];
    const float* W1  = (const float*)d_in[6];
    const float* as1 = (const float*)d_in[7];
    const float* ad1 = (const float*)d_in[8];
    const float* b1  = (const float*)d_in[9];
    const float* W2  = (const float*)d_in[10];
    const float* as2 = (const float*)d_in[11];
    const float* ad2 = (const float*)d_in[12];
    const float* b2  = (const float*)d_in[13];
    float* out = (float*)d_out;

    const dim3 gThreads(64, 4);
    const int gemmBlocks = 2048;
    const int edgeBlocks = (EE + 255) / 256;
    const int ndBlocks   = (NN * DD + 255) / 256;
    const int scatBlocks = (int)(((long long)EE * 16 + 255) / 256);

    k_detect<<<1, 256>>>(ei);
    k_convert<<<edgeBlocks, 256>>>(ei);

    // layer 0: out = relu(x @ W0 + b0)
    k_gemm<<<gemmBlocks, gThreads>>>(x, W0, b0, 1, nullptr, nullptr, out);

    // GAT layer 1
    k_gemm<<<gemmBlocks, gThreads>>>(out, W1, nullptr, 0, as1, ad1, nullptr);
    k_init<<<ndBlocks, 256>>>();
    k_edge_max<<<edgeBlocks, 256>>>();
    k_edge_sum<<<edgeBlocks, 256>>>();
    k_scatter<<<scatBlocks, 256>>>();
    k_finalize<<<ndBlocks, 256>>>(out, b1);

    // GAT layer 2
    k_gemm<<<gemmBlocks, gThreads>>>(out, W2, nullptr, 0, as2, ad2, nullptr);
    k_init<<<ndBlocks, 256>>>();
    k_edge_max<<<edgeBlocks, 256>>>();
    k_edge_sum<<<edgeBlocks, 256>>>();
    k_scatter<<<scatBlocks, 256>>>();
    k_finalize<<<ndBlocks, 256>>>(out, b2);
}

// round 4
// speedup vs baseline: 1.8389x; 1.8389x over previous
#include <cuda_runtime.h>
#include <cuda_bf16.h>

#define NN 50000
#define EE 800000
#define DD 64
#define NEG_INF __int_as_float(0xff800000)

// ---------------- scratch (static device globals; no allocation) ----------------
__device__ __align__(16) int   g_src[EE];
__device__ __align__(16) int   g_dst[EE];
__device__ __align__(16) int   g_csr_src[EE];     // src ids grouped by dst
__device__ __align__(16) float g_hx[NN * DD];
__device__ __align__(16) float g_ssrc[NN];
__device__ __align__(16) float g_sdst[NN];
__device__ __align__(16) int   g_deg[NN];
__device__ __align__(16) int   g_rowptr[NN + 1];
__device__ __align__(16) int   g_cursor[NN];
__device__ int g_is64;

// ---------------- CSR build ----------------

__global__ void k_detect(const int* __restrict__ ei) {
    __shared__ int any_nonzero;
    if (threadIdx.x == 0) any_nonzero = 0;
    __syncthreads();
    for (int i = threadIdx.x; i < 4096; i += blockDim.x)
        if (ei[2 * i + 1] != 0) any_nonzero = 1;   // benign race
    __syncthreads();
    if (threadIdx.x == 0) g_is64 = (any_nonzero == 0);
}

__global__ void k_zerodeg() {
    int i = blockIdx.x * blockDim.x + threadIdx.x;
    if (i < NN) g_deg[i] = 0;
}

// edge_index -> int32 src/dst (+ degree histogram of dst)
__global__ void k_convert(const int* __restrict__ ei) {
    int e = blockIdx.x * blockDim.x + threadIdx.x;
    if (e < EE) {
        int s, d;
        if (g_is64) { s = ei[2 * e];  d = ei[2 * (EE + e)]; }
        else        { s = ei[e];      d = ei[EE + e]; }
        s = min(max(s, 0), NN - 1);
        d = min(max(d, 0), NN - 1);
        g_src[e] = s;
        g_dst[e] = d;
        atomicAdd(&g_deg[d], 1);
    }
}

// single-block exclusive scan of g_deg -> g_rowptr / g_cursor
__global__ void k_scan() {
    __shared__ int s_part[1024];
    const int T = 1024;
    const int C = (NN + T - 1) / T;      // 49
    const int t = threadIdx.x;
    const int begin = t * C;
    const int end = min(begin + C, NN);
    int sum = 0;
    for (int j = begin; j < end; j++) sum += g_deg[j];
    s_part[t] = sum;
    __syncthreads();
    // Hillis-Steele inclusive scan
    for (int dlt = 1; dlt < T; dlt <<= 1) {
        int add = (t >= dlt) ? s_part[t - dlt] : 0;
        __syncthreads();
        s_part[t] += add;
        __syncthreads();
    }
    int run = s_part[t] - sum;           // exclusive prefix for this chunk
    for (int j = begin; j < end; j++) {
        g_rowptr[j] = run;
        g_cursor[j] = run;
        run += g_deg[j];
    }
    if (t == T - 1) g_rowptr[NN] = run;  // == EE
}

__global__ void k_fill() {
    int e = blockIdx.x * blockDim.x + threadIdx.x;
    if (e < EE) {
        int d = g_dst[e];
        int pos = atomicAdd(&g_cursor[d], 1);
        g_csr_src[pos] = g_src[e];
    }
}

// ---------------- GEMM: 64-row tile, 16x16 threads, 4x4 micro-tile ----------------
// hx = h @ W (+bias,+relu optional); if a_s: also ssrc/sdst epilogue dots.
__global__ void __launch_bounds__(256) k_gemm(
        const float* __restrict__ h, const float* __restrict__ W,
        const float* __restrict__ bias, int do_relu,
        const float* __restrict__ a_s, const float* __restrict__ a_d,
        float* __restrict__ out) {
    __shared__ float sW[64 * 64];
    __shared__ float sht[64 * 68];   // [k][row], padded pitch

    float* __restrict__ hx = out ? out : g_hx;

    const int tid = threadIdx.x;
    const int tx = tid & 15;         // col group
    const int ty = tid >> 4;         // row group
    const int r0 = blockIdx.x * 64;

    for (int i = tid; i < 64 * 64; i += 256) sW[i] = W[i];
    {
        const int col = tid & 63;
        const int rr0 = tid >> 6;    // 0..3
        #pragma unroll
        for (int rr = rr0; rr < 64; rr += 4) {
            const int r = r0 + rr;
            sht[col * 68 + rr] = (r < NN) ? h[r * 64 + col] : 0.0f;
        }
    }
    __syncthreads();

    float acc[4][4];
    #pragma unroll
    for (int i = 0; i < 4; i++)
        #pragma unroll
        for (int j = 0; j < 4; j++) acc[i][j] = 0.0f;

    #pragma unroll 8
    for (int k = 0; k < 64; k++) {
        const float4 a = *(const float4*)(sht + k * 68 + ty * 4);
        const float4 b = *(const float4*)(sW  + k * 64 + tx * 4);
        acc[0][0] = fmaf(a.x, b.x, acc[0][0]); acc[0][1] = fmaf(a.x, b.y, acc[0][1]);
        acc[0][2] = fmaf(a.x, b.z, acc[0][2]); acc[0][3] = fmaf(a.x, b.w, acc[0][3]);
        acc[1][0] = fmaf(a.y, b.x, acc[1][0]); acc[1][1] = fmaf(a.y, b.y, acc[1][1]);
        acc[1][2] = fmaf(a.y, b.z, acc[1][2]); acc[1][3] = fmaf(a.y, b.w, acc[1][3]);
        acc[2][0] = fmaf(a.z, b.x, acc[2][0]); acc[2][1] = fmaf(a.z, b.y, acc[2][1]);
        acc[2][2] = fmaf(a.z, b.z, acc[2][2]); acc[2][3] = fmaf(a.z, b.w, acc[2][3]);
        acc[3][0] = fmaf(a.w, b.x, acc[3][0]); acc[3][1] = fmaf(a.w, b.y, acc[3][1]);
        acc[3][2] = fmaf(a.w, b.z, acc[3][2]); acc[3][3] = fmaf(a.w, b.w, acc[3][3]);
    }

    float4 bia = make_float4(0.f, 0.f, 0.f, 0.f);
    if (bias) bia = *(const float4*)(bias + tx * 4);
    float4 asv = make_float4(0.f, 0.f, 0.f, 0.f), adv = asv;
    if (a_s) { asv = *(const float4*)(a_s + tx * 4); adv = *(const float4*)(a_d + tx * 4); }

    #pragma unroll
    for (int i = 0; i < 4; i++) {
        const int r = r0 + ty * 4 + i;
        if (r >= NN) break;
        float4 v = make_float4(acc[i][0] + bia.x, acc[i][1] + bia.y,
                               acc[i][2] + bia.z, acc[i][3] + bia.w);
        if (do_relu) {
            v.x = fmaxf(v.x, 0.f); v.y = fmaxf(v.y, 0.f);
            v.z = fmaxf(v.z, 0.f); v.w = fmaxf(v.w, 0.f);
        }
        *(float4*)(hx + r * 64 + tx * 4) = v;
        if (a_s) {
            float vs = v.x * asv.x + v.y * asv.y + v.z * asv.z + v.w * asv.w;
            float vd = v.x * adv.x + v.y * adv.y + v.z * adv.z + v.w * adv.w;
            #pragma unroll
            for (int o = 8; o > 0; o >>= 1) {
                vs += __shfl_down_sync(0xffffffffu, vs, o, 16);
                vd += __shfl_down_sync(0xffffffffu, vd, o, 16);
            }
            if (tx == 0) { g_ssrc[r] = vs; g_sdst[r] = vd; }
        }
    }
}

// ---------------- fused GAT aggregate: one warp per dst node ----------------
// out[i] += relu( (1/ssum) * sum_j e_j * hx[src_j] + b )
__global__ void __launch_bounds__(256) k_gat(float* __restrict__ out,
                                             const float* __restrict__ bias) {
    const int warp = threadIdx.x >> 5;
    const int lane = threadIdx.x & 31;
    const int node = blockIdx.x * 8 + warp;
    if (node >= NN) return;

    const int base = g_rowptr[node];
    const int end  = g_rowptr[node + 1];
    const float sdi = g_sdst[node];

    // pass 1: max of leaky_relu(ssrc[src] + sdi)
    float mx = NEG_INF;
    for (int j = base + lane; j < end; j += 32) {
        float a = g_ssrc[g_csr_src[j]] + sdi;
        a = (a >= 0.f) ? a : 0.2f * a;
        mx = fmaxf(mx, a);
    }
    #pragma unroll
    for (int o = 16; o > 0; o >>= 1)
        mx = fmaxf(mx, __shfl_xor_sync(0xffffffffu, mx, o));

    // pass 2: sum of exp(alpha - mx)
    float sm = 0.f;
    for (int j = base + lane; j < end; j += 32) {
        float a = g_ssrc[g_csr_src[j]] + sdi;
        a = (a >= 0.f) ? a : 0.2f * a;
        sm += __expf(a - mx);
    }
    #pragma unroll
    for (int o = 16; o > 0; o >>= 1)
        sm += __shfl_xor_sync(0xffffffffu, sm, o);

    const float inv = (end > base) ? (1.0f / sm) : 0.0f;

    // pass 3: column-parallel accumulate (lane owns cols 2*lane, 2*lane+1)
    float ax = 0.f, ay = 0.f;
    int j = base;
    for (; j + 1 < end; j += 2) {
        const int s0 = g_csr_src[j];
        const int s1 = g_csr_src[j + 1];
        float a0 = g_ssrc[s0] + sdi; a0 = (a0 >= 0.f) ? a0 : 0.2f * a0;
        float a1 = g_ssrc[s1] + sdi; a1 = (a1 >= 0.f) ? a1 : 0.2f * a1;
        const float e0 = __expf(a0 - mx);
        const float e1 = __expf(a1 - mx);
        const float2 v0 = *(const float2*)(g_hx + s0 * 64 + lane * 2);
        const float2 v1 = *(const float2*)(g_hx + s1 * 64 + lane * 2);
        ax = fmaf(e0, v0.x, ax); ay = fmaf(e0, v0.y, ay);
        ax = fmaf(e1, v1.x, ax); ay = fmaf(e1, v1.y, ay);
    }
    if (j < end) {
        const int s0 = g_csr_src[j];
        float a0 = g_ssrc[s0] + sdi; a0 = (a0 >= 0.f) ? a0 : 0.2f * a0;
        const float e0 = __expf(a0 - mx);
        const float2 v0 = *(const float2*)(g_hx + s0 * 64 + lane * 2);
        ax = fmaf(e0, v0.x, ax); ay = fmaf(e0, v0.y, ay);
    }

    float2 ob = *(float2*)(out + node * 64 + lane * 2);
    const float bx = bias[lane * 2], by = bias[lane * 2 + 1];
    ob.x += fmaxf(ax * inv + bx, 0.f);
    ob.y += fmaxf(ay * inv + by, 0.f);
    *(float2*)(out + node * 64 + lane * 2) = ob;
}

// ---------------- launch ----------------
extern "C" void kernel_launch(void* const* d_in, const int* in_sizes, int n_in,
                              void* d_out, int out_size) {
    const float* x   = (const float*)d_in[0];
    const int*   ei  = (const int*)d_in[1];
    const float* W0  = (const float*)d_in[4];
    const float* b0  = (const float*)d_in[5];
    const float* W1  = (const float*)d_in[6];
    const float* as1 = (const float*)d_in[7];
    const float* ad1 = (const float*)d_in[8];
    const float* b1  = (const float*)d_in[9];
    const float* W2  = (const float*)d_in[10];
    const float* as2 = (const float*)d_in[11];
    const float* ad2 = (const float*)d_in[12];
    const float* b2  = (const float*)d_in[13];
    float* out = (float*)d_out;

    const int edgeBlocks = (EE + 255) / 256;
    const int gemmBlocks = (NN + 63) / 64;
    const int gatBlocks  = (NN + 7) / 8;

    k_detect<<<1, 256>>>(ei);
    k_zerodeg<<<(NN + 255) / 256, 256>>>();
    k_convert<<<edgeBlocks, 256>>>(ei);
    k_scan<<<1, 1024>>>();
    k_fill<<<edgeBlocks, 256>>>();

    // layer 0: out = relu(x @ W0 + b0)
    k_gemm<<<gemmBlocks, 256>>>(x, W0, b0, 1, nullptr, nullptr, out);

    // GAT layer 1
    k_gemm<<<gemmBlocks, 256>>>(out, W1, nullptr, 0, as1, ad1, nullptr);
    k_gat<<<gatBlocks, 256>>>(out, b1);

    // GAT layer 2
    k_gemm<<<gemmBlocks, 256>>>(out, W2, nullptr, 0, as2, ad2, nullptr);
    k_gat<<<gatBlocks, 256>>>(out, b2);
}

// round 5
// speedup vs baseline: 2.8519x; 1.5508x over previous
#include <cuda_runtime.h>
#include <cuda_bf16.h>

#define NN 50000
#define EE 800000
#define DD 64
#define NEG_INF __int_as_float(0xff800000)
#define SCAN_BLOCKS 49   // ceil(NN / 1024)

// ---------------- scratch (static device globals; no allocation) ----------------
__device__ __align__(16) int   g_src[EE];
__device__ __align__(16) int   g_dst[EE];
__device__ __align__(16) int   g_csr_src[EE];     // src ids grouped by dst
__device__ __align__(16) float g_hx[NN * DD];
__device__ __align__(16) float g_ssrc[NN];
__device__ __align__(16) float g_sdst[NN];
__device__ __align__(16) int   g_deg[NN];
__device__ __align__(16) int   g_rowptr[NN + 4];
__device__ __align__(16) int   g_cursor[NN];
__device__ __align__(16) int   g_bsum[64];
__device__ __align__(16) int   g_boff[64];
__device__ int g_is64;

// ---------------- CSR build ----------------

__global__ void k_detect(const int* __restrict__ ei) {
    __shared__ int any_nonzero;
    if (threadIdx.x == 0) any_nonzero = 0;
    __syncthreads();
    for (int i = threadIdx.x; i < 4096; i += blockDim.x)
        if (ei[2 * i + 1] != 0) any_nonzero = 1;   // benign race
    __syncthreads();
    if (threadIdx.x == 0) g_is64 = (any_nonzero == 0);
}

__global__ void k_zerodeg() {
    int i = blockIdx.x * blockDim.x + threadIdx.x;
    if (i < NN) g_deg[i] = 0;
}

// edge_index -> int32 src/dst (+ degree histogram of dst)
__global__ void k_convert(const int* __restrict__ ei) {
    int e = blockIdx.x * blockDim.x + threadIdx.x;
    if (e < EE) {
        int s, d;
        if (g_is64) { s = ei[2 * e];  d = ei[2 * (EE + e)]; }
        else        { s = ei[e];      d = ei[EE + e]; }
        s = min(max(s, 0), NN - 1);
        d = min(max(d, 0), NN - 1);
        g_src[e] = s;
        g_dst[e] = d;
        atomicAdd(&g_deg[d], 1);
    }
}

// ---- parallel exclusive scan of g_deg: 3 kernels ----

// pass 1: per-block (1024 elems) sums
__global__ void __launch_bounds__(256) k_scansum() {
    const int tid = threadIdx.x;
    const int lane = tid & 31, warp = tid >> 5;
    const int base = blockIdx.x * 1024 + tid * 4;
    int s = 0;
    if (base + 3 < NN) {
        const int4 v = *(const int4*)(g_deg + base);
        s = v.x + v.y + v.z + v.w;
    } else {
        #pragma unroll
        for (int i = 0; i < 4; i++) if (base + i < NN) s += g_deg[base + i];
    }
    #pragma unroll
    for (int o = 16; o > 0; o >>= 1) s += __shfl_xor_sync(0xffffffffu, s, o);
    __shared__ int ws[8];
    if (lane == 0) ws[warp] = s;
    __syncthreads();
    if (tid == 0) {
        int t = 0;
        #pragma unroll
        for (int i = 0; i < 8; i++) t += ws[i];
        g_bsum[blockIdx.x] = t;
    }
}

// pass 2: exclusive scan of SCAN_BLOCKS block sums (one tiny block)
__global__ void k_scanoff() {
    __shared__ int sh[64];
    const int t = threadIdx.x;
    int v = (t < SCAN_BLOCKS) ? g_bsum[t] : 0;
    sh[t] = v;
    __syncthreads();
    for (int d = 1; d < 64; d <<= 1) {
        int a = (t >= d) ? sh[t - d] : 0;
        __syncthreads();
        sh[t] += a;
        __syncthreads();
    }
    if (t < SCAN_BLOCKS) g_boff[t] = sh[t] - v;   // exclusive
}

// pass 3: per-block scan + offset -> rowptr & cursor
__global__ void __launch_bounds__(256) k_scanout() {
    const int tid = threadIdx.x;
    const int lane = tid & 31, warp = tid >> 5;
    const int base = blockIdx.x * 1024 + tid * 4;

    int4 v = make_int4(0, 0, 0, 0);
    if (base + 3 < NN) {
        v = *(const int4*)(g_deg + base);
    } else {
        if (base + 0 < NN) v.x = g_deg[base + 0];
        if (base + 1 < NN) v.y = g_deg[base + 1];
        if (base + 2 < NN) v.z = g_deg[base + 2];
        if (base + 3 < NN) v.w = g_deg[base + 3];
    }
    const int s0 = v.x, s1 = s0 + v.y, s2 = s1 + v.z, s3 = s2 + v.w;
    const int tot = s3;

    // warp inclusive scan of tot
    int inc = tot;
    #pragma unroll
    for (int d = 1; d < 32; d <<= 1) {
        int a = __shfl_up_sync(0xffffffffu, inc, d);
        if (lane >= d) inc += a;
    }
    __shared__ int wtot[8];
    if (lane == 31) wtot[warp] = inc;
    __syncthreads();
    int woff = 0;
    for (int i = 0; i < warp; i++) woff += wtot[i];

    const int off = g_boff[blockIdx.x] + woff + (inc - tot);  // exclusive thread offset
    const int4 rp = make_int4(off, off + s0, off + s1, off + s2);
    if (base + 3 < NN) {
        *(int4*)(g_rowptr + base) = rp;
        *(int4*)(g_cursor + base) = rp;
    } else {
        if (base + 0 < NN) { g_rowptr[base + 0] = rp.x; g_cursor[base + 0] = rp.x; }
        if (base + 1 < NN) { g_rowptr[base + 1] = rp.y; g_cursor[base + 1] = rp.y; }
        if (base + 2 < NN) { g_rowptr[base + 2] = rp.z; g_cursor[base + 2] = rp.z; }
        if (base + 3 < NN) { g_rowptr[base + 3] = rp.w; g_cursor[base + 3] = rp.w; }
    }
    if (blockIdx.x == 0 && tid == 0) g_rowptr[NN] = EE;  // total degree == EE
}

__global__ void k_fill() {
    int e = blockIdx.x * blockDim.x + threadIdx.x;
    if (e < EE) {
        int d = g_dst[e];
        int pos = atomicAdd(&g_cursor[d], 1);
        g_csr_src[pos] = g_src[e];
    }
}

// ---------------- GEMM: 64-row tile, 16x16 threads, 4x4 micro-tile ----------------
__global__ void __launch_bounds__(256) k_gemm(
        const float* __restrict__ h, const float* __restrict__ W,
        const float* __restrict__ bias, int do_relu,
        const float* __restrict__ a_s, const float* __restrict__ a_d,
        float* __restrict__ out) {
    __shared__ float sW[64 * 64];
    __shared__ float sht[64 * 68];   // [k][row], padded pitch

    float* __restrict__ hx = out ? out : g_hx;

    const int tid = threadIdx.x;
    const int tx = tid & 15;         // col group
    const int ty = tid >> 4;         // row group
    const int r0 = blockIdx.x * 64;

    for (int i = tid; i < 64 * 64; i += 256) sW[i] = W[i];
    {
        const int col = tid & 63;
        const int rr0 = tid >> 6;    // 0..3
        #pragma unroll
        for (int rr = rr0; rr < 64; rr += 4) {
            const int r = r0 + rr;
            sht[col * 68 + rr] = (r < NN) ? h[r * 64 + col] : 0.0f;
        }
    }
    __syncthreads();

    float acc[4][4];
    #pragma unroll
    for (int i = 0; i < 4; i++)
        #pragma unroll
        for (int j = 0; j < 4; j++) acc[i][j] = 0.0f;

    #pragma unroll 8
    for (int k = 0; k < 64; k++) {
        const float4 a = *(const float4*)(sht + k * 68 + ty * 4);
        const float4 b = *(const float4*)(sW  + k * 64 + tx * 4);
        acc[0][0] = fmaf(a.x, b.x, acc[0][0]); acc[0][1] = fmaf(a.x, b.y, acc[0][1]);
        acc[0][2] = fmaf(a.x, b.z, acc[0][2]); acc[0][3] = fmaf(a.x, b.w, acc[0][3]);
        acc[1][0] = fmaf(a.y, b.x, acc[1][0]); acc[1][1] = fmaf(a.y, b.y, acc[1][1]);
        acc[1][2] = fmaf(a.y, b.z, acc[1][2]); acc[1][3] = fmaf(a.y, b.w, acc[1][3]);
        acc[2][0] = fmaf(a.z, b.x, acc[2][0]); acc[2][1] = fmaf(a.z, b.y, acc[2][1]);
        acc[2][2] = fmaf(a.z, b.z, acc[2][2]); acc[2][3] = fmaf(a.z, b.w, acc[2][3]);
        acc[3][0] = fmaf(a.w, b.x, acc[3][0]); acc[3][1] = fmaf(a.w, b.y, acc[3][1]);
        acc[3][2] = fmaf(a.w, b.z, acc[3][2]); acc[3][3] = fmaf(a.w, b.w, acc[3][3]);
    }

    float4 bia = make_float4(0.f, 0.f, 0.f, 0.f);
    if (bias) bia = *(const float4*)(bias + tx * 4);
    float4 asv = make_float4(0.f, 0.f, 0.f, 0.f), adv = asv;
    if (a_s) { asv = *(const float4*)(a_s + tx * 4); adv = *(const float4*)(a_d + tx * 4); }

    #pragma unroll
    for (int i = 0; i < 4; i++) {
        const int r = r0 + ty * 4 + i;
        if (r >= NN) break;
        float4 v = make_float4(acc[i][0] + bia.x, acc[i][1] + bia.y,
                               acc[i][2] + bia.z, acc[i][3] + bia.w);
        if (do_relu) {
            v.x = fmaxf(v.x, 0.f); v.y = fmaxf(v.y, 0.f);
            v.z = fmaxf(v.z, 0.f); v.w = fmaxf(v.w, 0.f);
        }
        *(float4*)(hx + r * 64 + tx * 4) = v;
        if (a_s) {
            float vs = v.x * asv.x + v.y * asv.y + v.z * asv.z + v.w * asv.w;
            float vd = v.x * adv.x + v.y * adv.y + v.z * adv.z + v.w * adv.w;
            #pragma unroll
            for (int o = 8; o > 0; o >>= 1) {
                vs += __shfl_down_sync(0xffffffffu, vs, o, 16);
                vd += __shfl_down_sync(0xffffffffu, vd, o, 16);
            }
            if (tx == 0) { g_ssrc[r] = vs; g_sdst[r] = vd; }
        }
    }
}

// ---------------- fused GAT aggregate: one warp per dst node ----------------
__global__ void __launch_bounds__(256) k_gat(float* __restrict__ out,
                                             const float* __restrict__ bias) {
    const int warp = threadIdx.x >> 5;
    const int lane = threadIdx.x & 31;
    const int node = blockIdx.x * 8 + warp;
    if (node >= NN) return;

    const int base = g_rowptr[node];
    const int end  = g_rowptr[node + 1];
    const float sdi = g_sdst[node];

    // pass 1: max of leaky_relu(ssrc[src] + sdi)
    float mx = NEG_INF;
    for (int j = base + lane; j < end; j += 32) {
        float a = g_ssrc[g_csr_src[j]] + sdi;
        a = (a >= 0.f) ? a : 0.2f * a;
        mx = fmaxf(mx, a);
    }
    #pragma unroll
    for (int o = 16; o > 0; o >>= 1)
        mx = fmaxf(mx, __shfl_xor_sync(0xffffffffu, mx, o));

    // pass 2: sum of exp(alpha - mx)
    float sm = 0.f;
    for (int j = base + lane; j < end; j += 32) {
        float a = g_ssrc[g_csr_src[j]] + sdi;
        a = (a >= 0.f) ? a : 0.2f * a;
        sm += __expf(a - mx);
    }
    #pragma unroll
    for (int o = 16; o > 0; o >>= 1)
        sm += __shfl_xor_sync(0xffffffffu, sm, o);

    const float inv = (end > base) ? (1.0f / sm) : 0.0f;

    // pass 3: column-parallel accumulate (lane owns cols 2*lane, 2*lane+1)
    float ax = 0.f, ay = 0.f;
    int j = base;
    for (; j + 1 < end; j += 2) {
        const int s0 = g_csr_src[j];
        const int s1 = g_csr_src[j + 1];
        float a0 = g_ssrc[s0] + sdi; a0 = (a0 >= 0.f) ? a0 : 0.2f * a0;
        float a1 = g_ssrc[s1] + sdi; a1 = (a1 >= 0.f) ? a1 : 0.2f * a1;
        const float e0 = __expf(a0 - mx);
        const float e1 = __expf(a1 - mx);
        const float2 v0 = *(const float2*)(g_hx + s0 * 64 + lane * 2);
        const float2 v1 = *(const float2*)(g_hx + s1 * 64 + lane * 2);
        ax = fmaf(e0, v0.x, ax); ay = fmaf(e0, v0.y, ay);
        ax = fmaf(e1, v1.x, ax); ay = fmaf(e1, v1.y, ay);
    }
    if (j < end) {
        const int s0 = g_csr_src[j];
        float a0 = g_ssrc[s0] + sdi; a0 = (a0 >= 0.f) ? a0 : 0.2f * a0;
        const float e0 = __expf(a0 - mx);
        const float2 v0 = *(const float2*)(g_hx + s0 * 64 + lane * 2);
        ax = fmaf(e0, v0.x, ax); ay = fmaf(e0, v0.y, ay);
    }

    float2 ob = *(float2*)(out + node * 64 + lane * 2);
    const float bx = bias[lane * 2], by = bias[lane * 2 + 1];
    ob.x += fmaxf(ax * inv + bx, 0.f);
    ob.y += fmaxf(ay * inv + by, 0.f);
    *(float2*)(out + node * 64 + lane * 2) = ob;
}

// ---------------- launch ----------------
extern "C" void kernel_launch(void* const* d_in, const int* in_sizes, int n_in,
                              void* d_out, int out_size) {
    const float* x   = (const float*)d_in[0];
    const int*   ei  = (const int*)d_in[1];
    const float* W0  = (const float*)d_in[4];
    const float* b0  = (const float*)d_in[5];
    const float* W1  = (const float*)d_in[6];
    const float* as1 = (const float*)d_in[7];
    const float* ad1 = (const float*)d_in[8];
    const float* b1  = (const float*)d_in[9];
    const float* W2  = (const float*)d_in[10];
    const float* as2 = (const float*)d_in[11];
    const float* ad2 = (const float*)d_in[12];
    const float* b2  = (const float*)d_in[13];
    float* out = (float*)d_out;

    const int edgeBlocks = (EE + 255) / 256;
    const int gemmBlocks = (NN + 63) / 64;
    const int gatBlocks  = (NN + 7) / 8;

    k_detect<<<1, 256>>>(ei);
    k_zerodeg<<<(NN + 255) / 256, 256>>>();
    k_convert<<<edgeBlocks, 256>>>(ei);
    k_scansum<<<SCAN_BLOCKS, 256>>>();
    k_scanoff<<<1, 64>>>();
    k_scanout<<<SCAN_BLOCKS, 256>>>();
    k_fill<<<edgeBlocks, 256>>>();

    // layer 0: out = relu(x @ W0 + b0)
    k_gemm<<<gemmBlocks, 256>>>(x, W0, b0, 1, nullptr, nullptr, out);

    // GAT layer 1
    k_gemm<<<gemmBlocks, 256>>>(out, W1, nullptr, 0, as1, ad1, nullptr);
    k_gat<<<gatBlocks, 256>>>(out, b1);

    // GAT layer 2
    k_gemm<<<gemmBlocks, 256>>>(out, W2, nullptr, 0, as2, ad2, nullptr);
    k_gat<<<gatBlocks, 256>>>(out, b2);
}

// round 6
// speedup vs baseline: 3.2976x; 1.1563x over previous
#include <cuda_runtime.h>
#include <cuda_bf16.h>

#define NN 50000
#define EE 800000
#define DD 64
#define NEG_INF __int_as_float(0xff800000)
#define SCAN_BLOCKS 49   // ceil(NN / 1024)

// ---------------- scratch (static device globals; no allocation) ----------------
__device__ __align__(16) int   g_src[EE];
__device__ __align__(16) int   g_dst[EE];
__device__ __align__(16) int   g_csr_src[EE];     // src ids grouped by dst
__device__ __align__(16) float g_hx[NN * DD];
__device__ __align__(16) float g_ssrc[NN];
__device__ __align__(16) float g_sdst[NN];
__device__ __align__(16) int   g_deg[NN];
__device__ __align__(16) int   g_rowptr[NN + 4];
__device__ __align__(16) int   g_cursor[NN];
__device__ __align__(16) int   g_bsum[64];
__device__ __align__(16) int   g_boff[64];
__device__ int g_is64;

// ---------------- CSR build ----------------

__global__ void k_detect(const int* __restrict__ ei) {
    __shared__ int any_nonzero;
    if (threadIdx.x == 0) any_nonzero = 0;
    __syncthreads();
    for (int i = threadIdx.x; i < 4096; i += blockDim.x)
        if (ei[2 * i + 1] != 0) any_nonzero = 1;   // benign race
    __syncthreads();
    if (threadIdx.x == 0) g_is64 = (any_nonzero == 0);
}

__global__ void k_zerodeg() {
    int i = blockIdx.x * blockDim.x + threadIdx.x;
    if (i < NN) g_deg[i] = 0;
}

__global__ void k_convert(const int* __restrict__ ei) {
    int e = blockIdx.x * blockDim.x + threadIdx.x;
    if (e < EE) {
        int s, d;
        if (g_is64) { s = ei[2 * e];  d = ei[2 * (EE + e)]; }
        else        { s = ei[e];      d = ei[EE + e]; }
        s = min(max(s, 0), NN - 1);
        d = min(max(d, 0), NN - 1);
        g_src[e] = s;
        g_dst[e] = d;
        atomicAdd(&g_deg[d], 1);
    }
}

// ---- parallel exclusive scan of g_deg: 3 kernels ----

__global__ void __launch_bounds__(256) k_scansum() {
    const int tid = threadIdx.x;
    const int lane = tid & 31, warp = tid >> 5;
    const int base = blockIdx.x * 1024 + tid * 4;
    int s = 0;
    if (base + 3 < NN) {
        const int4 v = *(const int4*)(g_deg + base);
        s = v.x + v.y + v.z + v.w;
    } else {
        #pragma unroll
        for (int i = 0; i < 4; i++) if (base + i < NN) s += g_deg[base + i];
    }
    #pragma unroll
    for (int o = 16; o > 0; o >>= 1) s += __shfl_xor_sync(0xffffffffu, s, o);
    __shared__ int ws[8];
    if (lane == 0) ws[warp] = s;
    __syncthreads();
    if (tid == 0) {
        int t = 0;
        #pragma unroll
        for (int i = 0; i < 8; i++) t += ws[i];
        g_bsum[blockIdx.x] = t;
    }
}

__global__ void k_scanoff() {
    __shared__ int sh[64];
    const int t = threadIdx.x;
    int v = (t < SCAN_BLOCKS) ? g_bsum[t] : 0;
    sh[t] = v;
    __syncthreads();
    for (int d = 1; d < 64; d <<= 1) {
        int a = (t >= d) ? sh[t - d] : 0;
        __syncthreads();
        sh[t] += a;
        __syncthreads();
    }
    if (t < SCAN_BLOCKS) g_boff[t] = sh[t] - v;   // exclusive
}

__global__ void __launch_bounds__(256) k_scanout() {
    const int tid = threadIdx.x;
    const int lane = tid & 31, warp = tid >> 5;
    const int base = blockIdx.x * 1024 + tid * 4;

    int4 v = make_int4(0, 0, 0, 0);
    if (base + 3 < NN) {
        v = *(const int4*)(g_deg + base);
    } else {
        if (base + 0 < NN) v.x = g_deg[base + 0];
        if (base + 1 < NN) v.y = g_deg[base + 1];
        if (base + 2 < NN) v.z = g_deg[base + 2];
        if (base + 3 < NN) v.w = g_deg[base + 3];
    }
    const int s0 = v.x, s1 = s0 + v.y, s2 = s1 + v.z, s3 = s2 + v.w;
    const int tot = s3;

    int inc = tot;
    #pragma unroll
    for (int d = 1; d < 32; d <<= 1) {
        int a = __shfl_up_sync(0xffffffffu, inc, d);
        if (lane >= d) inc += a;
    }
    __shared__ int wtot[8];
    if (lane == 31) wtot[warp] = inc;
    __syncthreads();
    int woff = 0;
    for (int i = 0; i < warp; i++) woff += wtot[i];

    const int off = g_boff[blockIdx.x] + woff + (inc - tot);
    const int4 rp = make_int4(off, off + s0, off + s1, off + s2);
    if (base + 3 < NN) {
        *(int4*)(g_rowptr + base) = rp;
        *(int4*)(g_cursor + base) = rp;
    } else {
        if (base + 0 < NN) { g_rowptr[base + 0] = rp.x; g_cursor[base + 0] = rp.x; }
        if (base + 1 < NN) { g_rowptr[base + 1] = rp.y; g_cursor[base + 1] = rp.y; }
        if (base + 2 < NN) { g_rowptr[base + 2] = rp.z; g_cursor[base + 2] = rp.z; }
        if (base + 3 < NN) { g_rowptr[base + 3] = rp.w; g_cursor[base + 3] = rp.w; }
    }
    if (blockIdx.x == 0 && tid == 0) g_rowptr[NN] = EE;
}

__global__ void k_fill() {
    int e = blockIdx.x * blockDim.x + threadIdx.x;
    if (e < EE) {
        int d = g_dst[e];
        int pos = atomicAdd(&g_cursor[d], 1);
        g_csr_src[pos] = g_src[e];
    }
}

// ---------------- GEMM: 64-row tile, 16x16 threads, 4x4 micro-tile ----------------
__global__ void __launch_bounds__(256) k_gemm(
        const float* __restrict__ h, const float* __restrict__ W,
        const float* __restrict__ bias, int do_relu,
        const float* __restrict__ a_s, const float* __restrict__ a_d,
        float* __restrict__ out) {
    __shared__ float sW[64 * 64];
    __shared__ float sht[64 * 68];   // [k][row], padded pitch

    float* __restrict__ hx = out ? out : g_hx;

    const int tid = threadIdx.x;
    const int tx = tid & 15;
    const int ty = tid >> 4;
    const int r0 = blockIdx.x * 64;

    for (int i = tid; i < 64 * 64; i += 256) sW[i] = W[i];
    {
        const int col = tid & 63;
        const int rr0 = tid >> 6;
        #pragma unroll
        for (int rr = rr0; rr < 64; rr += 4) {
            const int r = r0 + rr;
            sht[col * 68 + rr] = (r < NN) ? h[r * 64 + col] : 0.0f;
        }
    }
    __syncthreads();

    float acc[4][4];
    #pragma unroll
    for (int i = 0; i < 4; i++)
        #pragma unroll
        for (int j = 0; j < 4; j++) acc[i][j] = 0.0f;

    #pragma unroll 8
    for (int k = 0; k < 64; k++) {
        const float4 a = *(const float4*)(sht + k * 68 + ty * 4);
        const float4 b = *(const float4*)(sW  + k * 64 + tx * 4);
        acc[0][0] = fmaf(a.x, b.x, acc[0][0]); acc[0][1] = fmaf(a.x, b.y, acc[0][1]);
        acc[0][2] = fmaf(a.x, b.z, acc[0][2]); acc[0][3] = fmaf(a.x, b.w, acc[0][3]);
        acc[1][0] = fmaf(a.y, b.x, acc[1][0]); acc[1][1] = fmaf(a.y, b.y, acc[1][1]);
        acc[1][2] = fmaf(a.y, b.z, acc[1][2]); acc[1][3] = fmaf(a.y, b.w, acc[1][3]);
        acc[2][0] = fmaf(a.z, b.x, acc[2][0]); acc[2][1] = fmaf(a.z, b.y, acc[2][1]);
        acc[2][2] = fmaf(a.z, b.z, acc[2][2]); acc[2][3] = fmaf(a.z, b.w, acc[2][3]);
        acc[3][0] = fmaf(a.w, b.x, acc[3][0]); acc[3][1] = fmaf(a.w, b.y, acc[3][1]);
        acc[3][2] = fmaf(a.w, b.z, acc[3][2]); acc[3][3] = fmaf(a.w, b.w, acc[3][3]);
    }

    float4 bia = make_float4(0.f, 0.f, 0.f, 0.f);
    if (bias) bia = *(const float4*)(bias + tx * 4);
    float4 asv = make_float4(0.f, 0.f, 0.f, 0.f), adv = asv;
    if (a_s) { asv = *(const float4*)(a_s + tx * 4); adv = *(const float4*)(a_d + tx * 4); }

    #pragma unroll
    for (int i = 0; i < 4; i++) {
        const int r = r0 + ty * 4 + i;
        if (r >= NN) break;
        float4 v = make_float4(acc[i][0] + bia.x, acc[i][1] + bia.y,
                               acc[i][2] + bia.z, acc[i][3] + bia.w);
        if (do_relu) {
            v.x = fmaxf(v.x, 0.f); v.y = fmaxf(v.y, 0.f);
            v.z = fmaxf(v.z, 0.f); v.w = fmaxf(v.w, 0.f);
        }
        *(float4*)(hx + r * 64 + tx * 4) = v;
        if (a_s) {
            float vs = v.x * asv.x + v.y * asv.y + v.z * asv.z + v.w * asv.w;
            float vd = v.x * adv.x + v.y * adv.y + v.z * adv.z + v.w * adv.w;
            #pragma unroll
            for (int o = 8; o > 0; o >>= 1) {
                vs += __shfl_down_sync(0xffffffffu, vs, o, 16);
                vd += __shfl_down_sync(0xffffffffu, vd, o, 16);
            }
            if (tx == 0) { g_ssrc[r] = vs; g_sdst[r] = vd; }
        }
    }
}

// ---------------- fused GAT aggregate: one warp per dst node ----------------
// Two passes: (1) max; (2) merged exp-sum + float4 column gather with
// 2-edge half-warp parallelism (16 lanes x float4 = full 256B row per edge).
__global__ void __launch_bounds__(256) k_gat(float* __restrict__ out,
                                             const float* __restrict__ bias) {
    const int warp = threadIdx.x >> 5;
    const int lane = threadIdx.x & 31;
    const int node = blockIdx.x * 8 + warp;
    if (node >= NN) return;

    const int base = g_rowptr[node];
    const int end  = g_rowptr[node + 1];
    const float sdi = g_sdst[node];

    // pass 1: max of leaky_relu(ssrc[src] + sdi), striped
    float mx = NEG_INF;
    for (int j = base + lane; j < end; j += 32) {
        float a = g_ssrc[g_csr_src[j]] + sdi;
        a = (a >= 0.f) ? a : 0.2f * a;
        mx = fmaxf(mx, a);
    }
    #pragma unroll
    for (int o = 16; o > 0; o >>= 1)
        mx = fmaxf(mx, __shfl_xor_sync(0xffffffffu, mx, o));

    // pass 2: merged exp-sum + weighted feature gather
    const int half = lane >> 4;   // which edge of the pair
    const int sub  = lane & 15;   // owns cols sub*4 .. sub*4+3
    float4 acc = make_float4(0.f, 0.f, 0.f, 0.f);
    float esum = 0.f;
    #pragma unroll 2
    for (int j = base + half; j < end; j += 2) {
        const int s = g_csr_src[j];
        float a = g_ssrc[s] + sdi;
        a = (a >= 0.f) ? a : 0.2f * a;
        const float e = __expf(a - mx);
        const float4 v = *(const float4*)(g_hx + s * 64 + sub * 4);
        acc.x = fmaf(e, v.x, acc.x);
        acc.y = fmaf(e, v.y, acc.y);
        acc.z = fmaf(e, v.z, acc.z);
        acc.w = fmaf(e, v.w, acc.w);
        esum += e;
    }
    // combine the two halves
    esum  += __shfl_xor_sync(0xffffffffu, esum,  16);
    acc.x += __shfl_xor_sync(0xffffffffu, acc.x, 16);
    acc.y += __shfl_xor_sync(0xffffffffu, acc.y, 16);
    acc.z += __shfl_xor_sync(0xffffffffu, acc.z, 16);
    acc.w += __shfl_xor_sync(0xffffffffu, acc.w, 16);

    const float inv = (end > base) ? (1.0f / esum) : 0.0f;

    if (half == 0) {
        float4 ob = *(float4*)(out + node * 64 + sub * 4);
        const float4 bb = *(const float4*)(bias + sub * 4);
        ob.x += fmaxf(fmaf(acc.x, inv, bb.x), 0.f);
        ob.y += fmaxf(fmaf(acc.y, inv, bb.y), 0.f);
        ob.z += fmaxf(fmaf(acc.z, inv, bb.z), 0.f);
        ob.w += fmaxf(fmaf(acc.w, inv, bb.w), 0.f);
        *(float4*)(out + node * 64 + sub * 4) = ob;
    }
}

// ---------------- launch ----------------
extern "C" void kernel_launch(void* const* d_in, const int* in_sizes, int n_in,
                              void* d_out, int out_size) {
    const float* x   = (const float*)d_in[0];
    const int*   ei  = (const int*)d_in[1];
    const float* W0  = (const float*)d_in[4];
    const float* b0  = (const float*)d_in[5];
    const float* W1  = (const float*)d_in[6];
    const float* as1 = (const float*)d_in[7];
    const float* ad1 = (const float*)d_in[8];
    const float* b1  = (const float*)d_in[9];
    const float* W2  = (const float*)d_in[10];
    const float* as2 = (const float*)d_in[11];
    const float* ad2 = (const float*)d_in[12];
    const float* b2  = (const float*)d_in[13];
    float* out = (float*)d_out;

    const int edgeBlocks = (EE + 255) / 256;
    const int gemmBlocks = (NN + 63) / 64;
    const int gatBlocks  = (NN + 7) / 8;

    k_detect<<<1, 256>>>(ei);
    k_zerodeg<<<(NN + 255) / 256, 256>>>();
    k_convert<<<edgeBlocks, 256>>>(ei);
    k_scansum<<<SCAN_BLOCKS, 256>>>();
    k_scanoff<<<1, 64>>>();
    k_scanout<<<SCAN_BLOCKS, 256>>>();
    k_fill<<<edgeBlocks, 256>>>();

    // layer 0: out = relu(x @ W0 + b0)
    k_gemm<<<gemmBlocks, 256>>>(x, W0, b0, 1, nullptr, nullptr, out);

    // GAT layer 1
    k_gemm<<<gemmBlocks, 256>>>(out, W1, nullptr, 0, as1, ad1, nullptr);
    k_gat<<<gatBlocks, 256>>>(out, b1);

    // GAT layer 2
    k_gemm<<<gemmBlocks, 256>>>(out, W2, nullptr, 0, as2, ad2, nullptr);
    k_gat<<<gatBlocks, 256>>>(out, b2);
}

// round 8
// speedup vs baseline: 3.3735x; 1.0230x over previous
#include <cuda_runtime.h>
#include <cuda_fp16.h>

#define NN 50000
#define EE 800000
#define DD 64
#define NEG_INF __int_as_float(0xff800000)
#define SCAN_BLOCKS 49   // ceil(NN / 1024)

// ---------------- scratch (static device globals; no allocation) ----------------
__device__ __align__(16) int    g_src[EE];
__device__ __align__(16) int    g_dst[EE];
__device__ __align__(16) int    g_csr_src[EE];     // src ids grouped by dst
__device__ __align__(16) __half g_hxh[NN * DD];    // fp16 feature matrix (gather source)
__device__ __align__(16) float  g_ssrc[NN];
__device__ __align__(16) float  g_sdst[NN];
__device__ __align__(16) int    g_deg[NN];
__device__ __align__(16) int    g_rowptr[NN + 4];
__device__ __align__(16) int    g_cursor[NN];
__device__ __align__(16) int    g_bsum[64];
__device__ __align__(16) int    g_boff[64];
__device__ int g_is64;

// ---------------- CSR build ----------------

// block 0: detect int64-vs-int32 layout; all blocks: zero degree histogram
__global__ void k_detect_zero(const int* __restrict__ ei) {
    const int i = blockIdx.x * blockDim.x + threadIdx.x;
    if (i < NN) g_deg[i] = 0;
    if (blockIdx.x == 0) {
        __shared__ int any_nonzero;
        if (threadIdx.x == 0) any_nonzero = 0;
        __syncthreads();
        for (int j = threadIdx.x; j < 4096; j += blockDim.x)
            if (ei[2 * j + 1] != 0) any_nonzero = 1;   // benign race
        __syncthreads();
        if (threadIdx.x == 0) g_is64 = (any_nonzero == 0);
    }
}

__global__ void k_convert(const int* __restrict__ ei) {
    int e = blockIdx.x * blockDim.x + threadIdx.x;
    if (e < EE) {
        int s, d;
        if (g_is64) { s = ei[2 * e];  d = ei[2 * (EE + e)]; }
        else        { s = ei[e];      d = ei[EE + e]; }
        s = min(max(s, 0), NN - 1);
        d = min(max(d, 0), NN - 1);
        g_src[e] = s;
        g_dst[e] = d;
        atomicAdd(&g_deg[d], 1);
    }
}

// ---- parallel exclusive scan of g_deg: 3 kernels ----

__global__ void __launch_bounds__(256) k_scansum() {
    const int tid = threadIdx.x;
    const int lane = tid & 31, warp = tid >> 5;
    const int base = blockIdx.x * 1024 + tid * 4;
    int s = 0;
    if (base + 3 < NN) {
        const int4 v = *(const int4*)(g_deg + base);
        s = v.x + v.y + v.z + v.w;
    } else {
        #pragma unroll
        for (int i = 0; i < 4; i++) if (base + i < NN) s += g_deg[base + i];
    }
    #pragma unroll
    for (int o = 16; o > 0; o >>= 1) s += __shfl_xor_sync(0xffffffffu, s, o);
    __shared__ int ws[8];
    if (lane == 0) ws[warp] = s;
    __syncthreads();
    if (tid == 0) {
        int t = 0;
        #pragma unroll
        for (int i = 0; i < 8; i++) t += ws[i];
        g_bsum[blockIdx.x] = t;
    }
}

__global__ void k_scanoff() {
    __shared__ int sh[64];
    const int t = threadIdx.x;
    int v = (t < SCAN_BLOCKS) ? g_bsum[t] : 0;
    sh[t] = v;
    __syncthreads();
    for (int d = 1; d < 64; d <<= 1) {
        int a = (t >= d) ? sh[t - d] : 0;
        __syncthreads();
        sh[t] += a;
        __syncthreads();
    }
    if (t < SCAN_BLOCKS) g_boff[t] = sh[t] - v;   // exclusive
}

__global__ void __launch_bounds__(256) k_scanout() {
    const int tid = threadIdx.x;
    const int lane = tid & 31, warp = tid >> 5;
    const int base = blockIdx.x * 1024 + tid * 4;

    int4 v = make_int4(0, 0, 0, 0);
    if (base + 3 < NN) {
        v = *(const int4*)(g_deg + base);
    } else {
        if (base + 0 < NN) v.x = g_deg[base + 0];
        if (base + 1 < NN) v.y = g_deg[base + 1];
        if (base + 2 < NN) v.z = g_deg[base + 2];
        if (base + 3 < NN) v.w = g_deg[base + 3];
    }
    const int s0 = v.x, s1 = s0 + v.y, s2 = s1 + v.z, s3 = s2 + v.w;
    const int tot = s3;

    int inc = tot;
    #pragma unroll
    for (int d = 1; d < 32; d <<= 1) {
        int a = __shfl_up_sync(0xffffffffu, inc, d);
        if (lane >= d) inc += a;
    }
    __shared__ int wtot[8];
    if (lane == 31) wtot[warp] = inc;
    __syncthreads();
    int woff = 0;
    for (int i = 0; i < warp; i++) woff += wtot[i];

    const int off = g_boff[blockIdx.x] + woff + (inc - tot);
    const int4 rp = make_int4(off, off + s0, off + s1, off + s2);
    if (base + 3 < NN) {
        *(int4*)(g_rowptr + base) = rp;
        *(int4*)(g_cursor + base) = rp;
    } else {
        if (base + 0 < NN) { g_rowptr[base + 0] = rp.x; g_cursor[base + 0] = rp.x; }
        if (base + 1 < NN) { g_rowptr[base + 1] = rp.y; g_cursor[base + 1] = rp.y; }
        if (base + 2 < NN) { g_rowptr[base + 2] = rp.z; g_cursor[base + 2] = rp.z; }
        if (base + 3 < NN) { g_rowptr[base + 3] = rp.w; g_cursor[base + 3] = rp.w; }
    }
    if (blockIdx.x == 0 && tid == 0) g_rowptr[NN] = EE;
}

__global__ void k_fill() {
    int e = blockIdx.x * blockDim.x + threadIdx.x;
    if (e < EE) {
        int d = g_dst[e];
        int pos = atomicAdd(&g_cursor[d], 1);
        g_csr_src[pos] = g_src[e];
    }
}

// ---------------- GEMM: 64-row tile, 16x16 threads, 4x4 micro-tile ----------------
// If out != nullptr: write fp32 rows to out. Else: write fp16 rows to g_hxh
// (gather source) and the attention-logit dots to g_ssrc/g_sdst.
__global__ void __launch_bounds__(256) k_gemm(
        const float* __restrict__ h, const float* __restrict__ W,
        const float* __restrict__ bias, int do_relu,
        const float* __restrict__ a_s, const float* __restrict__ a_d,
        float* __restrict__ out) {
    __shared__ float sW[64 * 64];
    __shared__ float sht[64 * 68];   // [k][row], padded pitch

    const int tid = threadIdx.x;
    const int tx = tid & 15;
    const int ty = tid >> 4;
    const int r0 = blockIdx.x * 64;

    for (int i = tid; i < 64 * 64; i += 256) sW[i] = W[i];
    {
        const int col = tid & 63;
        const int rr0 = tid >> 6;
        #pragma unroll
        for (int rr = rr0; rr < 64; rr += 4) {
            const int r = r0 + rr;
            sht[col * 68 + rr] = (r < NN) ? h[r * 64 + col] : 0.0f;
        }
    }
    __syncthreads();

    float acc[4][4];
    #pragma unroll
    for (int i = 0; i < 4; i++)
        #pragma unroll
        for (int j = 0; j < 4; j++) acc[i][j] = 0.0f;

    #pragma unroll 8
    for (int k = 0; k < 64; k++) {
        const float4 a = *(const float4*)(sht + k * 68 + ty * 4);
        const float4 b = *(const float4*)(sW  + k * 64 + tx * 4);
        acc[0][0] = fmaf(a.x, b.x, acc[0][0]); acc[0][1] = fmaf(a.x, b.y, acc[0][1]);
        acc[0][2] = fmaf(a.x, b.z, acc[0][2]); acc[0][3] = fmaf(a.x, b.w, acc[0][3]);
        acc[1][0] = fmaf(a.y, b.x, acc[1][0]); acc[1][1] = fmaf(a.y, b.y, acc[1][1]);
        acc[1][2] = fmaf(a.y, b.z, acc[1][2]); acc[1][3] = fmaf(a.y, b.w, acc[1][3]);
        acc[2][0] = fmaf(a.z, b.x, acc[2][0]); acc[2][1] = fmaf(a.z, b.y, acc[2][1]);
        acc[2][2] = fmaf(a.z, b.z, acc[2][2]); acc[2][3] = fmaf(a.z, b.w, acc[2][3]);
        acc[3][0] = fmaf(a.w, b.x, acc[3][0]); acc[3][1] = fmaf(a.w, b.y, acc[3][1]);
        acc[3][2] = fmaf(a.w, b.z, acc[3][2]); acc[3][3] = fmaf(a.w, b.w, acc[3][3]);
    }

    float4 bia = make_float4(0.f, 0.f, 0.f, 0.f);
    if (bias) bia = *(const float4*)(bias + tx * 4);
    float4 asv = make_float4(0.f, 0.f, 0.f, 0.f), adv = asv;
    if (a_s) { asv = *(const float4*)(a_s + tx * 4); adv = *(const float4*)(a_d + tx * 4); }

    #pragma unroll
    for (int i = 0; i < 4; i++) {
        const int r = r0 + ty * 4 + i;
        if (r >= NN) break;
        float4 v = make_float4(acc[i][0] + bia.x, acc[i][1] + bia.y,
                               acc[i][2] + bia.z, acc[i][3] + bia.w);
        if (do_relu) {
            v.x = fmaxf(v.x, 0.f); v.y = fmaxf(v.y, 0.f);
            v.z = fmaxf(v.z, 0.f); v.w = fmaxf(v.w, 0.f);
        }
        if (out) {
            *(float4*)(out + r * 64 + tx * 4) = v;
        } else {
            const __half2 p0 = __floats2half2_rn(v.x, v.y);
            const __half2 p1 = __floats2half2_rn(v.z, v.w);
            uint2 pk;
            pk.x = *(const unsigned int*)&p0;
            pk.y = *(const unsigned int*)&p1;
            *(uint2*)(g_hxh + r * 64 + tx * 4) = pk;
        }
        if (a_s) {
            float vs = v.x * asv.x + v.y * asv.y + v.z * asv.z + v.w * asv.w;
            float vd = v.x * adv.x + v.y * adv.y + v.z * adv.z + v.w * adv.w;
            #pragma unroll
            for (int o = 8; o > 0; o >>= 1) {
                vs += __shfl_down_sync(0xffffffffu, vs, o, 16);
                vd += __shfl_down_sync(0xffffffffu, vd, o, 16);
            }
            if (tx == 0) { g_ssrc[r] = vs; g_sdst[r] = vd; }
        }
    }
}

// ---------------- fused GAT aggregate: one warp per dst node ----------------
// pass 1: striped max. pass 2: merged exp-sum + fp16 gather with
// quarter-warp parallelism (8 lanes x 16B = one 128B row; 4 edges in flight).
__global__ void __launch_bounds__(256) k_gat(float* __restrict__ out,
                                             const float* __restrict__ bias) {
    const int warp = threadIdx.x >> 5;
    const int lane = threadIdx.x & 31;
    const int node = blockIdx.x * 8 + warp;
    if (node >= NN) return;

    const int base = g_rowptr[node];
    const int end  = g_rowptr[node + 1];
    const float sdi = g_sdst[node];

    // pass 1: max of leaky_relu(ssrc[src] + sdi)
    float mx = NEG_INF;
    for (int j = base + lane; j < end; j += 32) {
        float a = g_ssrc[g_csr_src[j]] + sdi;
        a = (a >= 0.f) ? a : 0.2f * a;
        mx = fmaxf(mx, a);
    }
    #pragma unroll
    for (int o = 16; o > 0; o >>= 1)
        mx = fmaxf(mx, __shfl_xor_sync(0xffffffffu, mx, o));

    // pass 2: merged exp-sum + fp16 feature gather
    const int quarter = lane >> 3;   // 0..3: which edge of the group of 4
    const int sub     = lane & 7;    // owns cols sub*8 .. sub*8+7
    float f[8];
    #pragma unroll
    for (int i = 0; i < 8; i++) f[i] = 0.f;
    float esum = 0.f;

    #pragma unroll 2
    for (int j = base + quarter; j < end; j += 4) {
        const int s = g_csr_src[j];
        float a = g_ssrc[s] + sdi;
        a = (a >= 0.f) ? a : 0.2f * a;
        const float e = __expf(a - mx);
        const uint4 raw = *(const uint4*)(g_hxh + s * 64 + sub * 8);
        const __half2* hp = (const __half2*)&raw;
        const float2 f0 = __half22float2(hp[0]);
        const float2 f1 = __half22float2(hp[1]);
        const float2 f2 = __half22float2(hp[2]);
        const float2 f3 = __half22float2(hp[3]);
        f[0] = fmaf(e, f0.x, f[0]); f[1] = fmaf(e, f0.y, f[1]);
        f[2] = fmaf(e, f1.x, f[2]); f[3] = fmaf(e, f1.y, f[3]);
        f[4] = fmaf(e, f2.x, f[4]); f[5] = fmaf(e, f2.y, f[5]);
        f[6] = fmaf(e, f3.x, f[6]); f[7] = fmaf(e, f3.y, f[7]);
        esum += e;
    }
    // combine the four quarters
    #pragma unroll
    for (int o = 8; o <= 16; o <<= 1) {
        esum += __shfl_xor_sync(0xffffffffu, esum, o);
        #pragma unroll
        for (int i = 0; i < 8; i++)
            f[i] += __shfl_xor_sync(0xffffffffu, f[i], o);
    }

    const float inv = (end > base) ? (1.0f / esum) : 0.0f;

    if (quarter == 0) {
        float4 ob0 = *(float4*)(out + node * 64 + sub * 8);
        float4 ob1 = *(float4*)(out + node * 64 + sub * 8 + 4);
        const float4 bb0 = *(const float4*)(bias + sub * 8);
        const float4 bb1 = *(const float4*)(bias + sub * 8 + 4);
        ob0.x += fmaxf(fmaf(f[0], inv, bb0.x), 0.f);
        ob0.y += fmaxf(fmaf(f[1], inv, bb0.y), 0.f);
        ob0.z += fmaxf(fmaf(f[2], inv, bb0.z), 0.f);
        ob0.w += fmaxf(fmaf(f[3], inv, bb0.w), 0.f);
        ob1.x += fmaxf(fmaf(f[4], inv, bb1.x), 0.f);
        ob1.y += fmaxf(fmaf(f[5], inv, bb1.y), 0.f);
        ob1.z += fmaxf(fmaf(f[6], inv, bb1.z), 0.f);
        ob1.w += fmaxf(fmaf(f[7], inv, bb1.w), 0.f);
        *(float4*)(out + node * 64 + sub * 8)     = ob0;
        *(float4*)(out + node * 64 + sub * 8 + 4) = ob1;
    }
}

// ---------------- launch ----------------
extern "C" void kernel_launch(void* const* d_in, const int* in_sizes, int n_in,
                              void* d_out, int out_size) {
    const float* x   = (const float*)d_in[0];
    const int*   ei  = (const int*)d_in[1];
    const float* W0  = (const float*)d_in[4];
    const float* b0  = (const float*)d_in[5];
    const float* W1  = (const float*)d_in[6];
    const float* as1 = (const float*)d_in[7];
    const float* ad1 = (const float*)d_in[8];
    const float* b1  = (const float*)d_in[9];
    const float* W2  = (const float*)d_in[10];
    const float* as2 = (const float*)d_in[11];
    const float* ad2 = (const float*)d_in[12];
    const float* b2  = (const float*)d_in[13];
    float* out = (float*)d_out;

    const int edgeBlocks = (EE + 255) / 256;
    const int gemmBlocks = (NN + 63) / 64;
    const int gatBlocks  = (NN + 7) / 8;

    k_detect_zero<<<(NN + 255) / 256, 256>>>(ei);
    k_convert<<<edgeBlocks, 256>>>(ei);
    k_scansum<<<SCAN_BLOCKS, 256>>>();
    k_scanoff<<<1, 64>>>();
    k_scanout<<<SCAN_BLOCKS, 256>>>();
    k_fill<<<edgeBlocks, 256>>>();

    // layer 0: out = relu(x @ W0 + b0)
    k_gemm<<<gemmBlocks, 256>>>(x, W0, b0, 1, nullptr, nullptr, out);

    // GAT layer 1
    k_gemm<<<gemmBlocks, 256>>>(out, W1, nullptr, 0, as1, ad1, nullptr);
    k_gat<<<gatBlocks, 256>>>(out, b1);

    // GAT layer 2
    k_gemm<<<gemmBlocks, 256>>>(out, W2, nullptr, 0, as2, ad2, nullptr);
    k_gat<<<gatBlocks, 256>>>(out, b2);
}

// round 9
// speedup vs baseline: 3.6060x; 1.0689x over previous
#include <cuda_runtime.h>
#include <cuda_fp16.h>

#define NN 50000
#define EE 800000
#define DD 64
#define SCAN_BLOCKS 49   // ceil(NN / 1024)

// ---------------- scratch (static device globals; no allocation) ----------------
__device__ __align__(16) int    g_csr_src[EE];     // src ids grouped by dst
__device__ __align__(16) __half g_hxh[NN * DD];    // fp16 feature matrix (gather source)
__device__ __align__(16) float  g_ssrc[NN];
__device__ __align__(16) float  g_sdst[NN];
__device__ __align__(16) int    g_deg[NN];
__device__ __align__(16) int    g_rowptr[NN + 4];
__device__ __align__(16) int    g_cursor[NN];
__device__ __align__(16) int    g_bsum[64];
__device__ int g_is64;

// ---------------- CSR build ----------------

// block 0: detect int64-vs-int32 layout; all blocks: zero degree histogram
__global__ void k_detect_zero(const int* __restrict__ ei) {
    const int i = blockIdx.x * blockDim.x + threadIdx.x;
    if (i < NN) g_deg[i] = 0;
    if (blockIdx.x == 0) {
        __shared__ int any_nonzero;
        if (threadIdx.x == 0) any_nonzero = 0;
        __syncthreads();
        for (int j = threadIdx.x; j < 4096; j += blockDim.x)
            if (ei[2 * j + 1] != 0) any_nonzero = 1;   // benign race
        __syncthreads();
        if (threadIdx.x == 0) g_is64 = (any_nonzero == 0);
    }
}

__device__ __forceinline__ int load_dst(const int* __restrict__ ei, int e, int is64) {
    int d = is64 ? ei[2 * (EE + e)] : ei[EE + e];
    return min(max(d, 0), NN - 1);
}
__device__ __forceinline__ int load_src(const int* __restrict__ ei, int e, int is64) {
    int s = is64 ? ei[2 * e] : ei[e];
    return min(max(s, 0), NN - 1);
}

// histogram of dst (reads edge_index directly)
__global__ void k_hist(const int* __restrict__ ei) {
    int e = blockIdx.x * blockDim.x + threadIdx.x;
    if (e < EE) atomicAdd(&g_deg[load_dst(ei, e, g_is64)], 1);
}

// pass 1 of scan: per-1024-chunk sums
__global__ void __launch_bounds__(256) k_scansum() {
    const int tid = threadIdx.x;
    const int lane = tid & 31, warp = tid >> 5;
    const int base = blockIdx.x * 1024 + tid * 4;
    int s = 0;
    if (base + 3 < NN) {
        const int4 v = *(const int4*)(g_deg + base);
        s = v.x + v.y + v.z + v.w;
    } else {
        #pragma unroll
        for (int i = 0; i < 4; i++) if (base + i < NN) s += g_deg[base + i];
    }
    #pragma unroll
    for (int o = 16; o > 0; o >>= 1) s += __shfl_xor_sync(0xffffffffu, s, o);
    __shared__ int ws[8];
    if (lane == 0) ws[warp] = s;
    __syncthreads();
    if (tid == 0) {
        int t = 0;
        #pragma unroll
        for (int i = 0; i < 8; i++) t += ws[i];
        g_bsum[blockIdx.x] = t;
    }
}

// pass 2: each block computes its own exclusive offset from g_bsum, then
// scans its 1024-element chunk -> rowptr & cursor
__global__ void __launch_bounds__(256) k_scanout() {
    const int tid = threadIdx.x;
    const int lane = tid & 31, warp = tid >> 5;
    const int base = blockIdx.x * 1024 + tid * 4;

    // block-level exclusive offset: sum of g_bsum[0 .. bid-1] (<= 48 values)
    __shared__ int s_boff;
    if (warp == 0) {
        int v = 0;
        if (lane < blockIdx.x) v = g_bsum[lane];
        if (lane + 32 < blockIdx.x) v += g_bsum[lane + 32];
        #pragma unroll
        for (int o = 16; o > 0; o >>= 1) v += __shfl_xor_sync(0xffffffffu, v, o);
        if (lane == 0) s_boff = v;
    }

    int4 v = make_int4(0, 0, 0, 0);
    if (base + 3 < NN) {
        v = *(const int4*)(g_deg + base);
    } else {
        if (base + 0 < NN) v.x = g_deg[base + 0];
        if (base + 1 < NN) v.y = g_deg[base + 1];
        if (base + 2 < NN) v.z = g_deg[base + 2];
        if (base + 3 < NN) v.w = g_deg[base + 3];
    }
    const int s0 = v.x, s1 = s0 + v.y, s2 = s1 + v.z, s3 = s2 + v.w;
    const int tot = s3;

    int inc = tot;
    #pragma unroll
    for (int d = 1; d < 32; d <<= 1) {
        int a = __shfl_up_sync(0xffffffffu, inc, d);
        if (lane >= d) inc += a;
    }
    __shared__ int wtot[8];
    if (lane == 31) wtot[warp] = inc;
    __syncthreads();
    int woff = 0;
    for (int i = 0; i < warp; i++) woff += wtot[i];

    const int off = s_boff + woff + (inc - tot);
    const int4 rp = make_int4(off, off + s0, off + s1, off + s2);
    if (base + 3 < NN) {
        *(int4*)(g_rowptr + base) = rp;
        *(int4*)(g_cursor + base) = rp;
    } else {
        if (base + 0 < NN) { g_rowptr[base + 0] = rp.x; g_cursor[base + 0] = rp.x; }
        if (base + 1 < NN) { g_rowptr[base + 1] = rp.y; g_cursor[base + 1] = rp.y; }
        if (base + 2 < NN) { g_rowptr[base + 2] = rp.z; g_cursor[base + 2] = rp.z; }
        if (base + 3 < NN) { g_rowptr[base + 3] = rp.w; g_cursor[base + 3] = rp.w; }
    }
    if (blockIdx.x == 0 && tid == 0) g_rowptr[NN] = EE;
}

// fill CSR (reads edge_index directly)
__global__ void k_fill(const int* __restrict__ ei) {
    int e = blockIdx.x * blockDim.x + threadIdx.x;
    if (e < EE) {
        const int is64 = g_is64;
        const int d = load_dst(ei, e, is64);
        const int s = load_src(ei, e, is64);
        int pos = atomicAdd(&g_cursor[d], 1);
        g_csr_src[pos] = s;
    }
}

// ---------------- GEMM: 64-row tile, 16x16 threads, 4x4 micro-tile ----------------
__global__ void __launch_bounds__(256) k_gemm(
        const float* __restrict__ h, const float* __restrict__ W,
        const float* __restrict__ bias, int do_relu,
        const float* __restrict__ a_s, const float* __restrict__ a_d,
        float* __restrict__ out) {
    __shared__ float sW[64 * 64];
    __shared__ float sht[64 * 68];   // [k][row], padded pitch

    const int tid = threadIdx.x;
    const int tx = tid & 15;
    const int ty = tid >> 4;
    const int r0 = blockIdx.x * 64;

    for (int i = tid; i < 64 * 64; i += 256) sW[i] = W[i];
    {
        const int col = tid & 63;
        const int rr0 = tid >> 6;
        #pragma unroll
        for (int rr = rr0; rr < 64; rr += 4) {
            const int r = r0 + rr;
            sht[col * 68 + rr] = (r < NN) ? h[r * 64 + col] : 0.0f;
        }
    }
    __syncthreads();

    float acc[4][4];
    #pragma unroll
    for (int i = 0; i < 4; i++)
        #pragma unroll
        for (int j = 0; j < 4; j++) acc[i][j] = 0.0f;

    #pragma unroll 8
    for (int k = 0; k < 64; k++) {
        const float4 a = *(const float4*)(sht + k * 68 + ty * 4);
        const float4 b = *(const float4*)(sW  + k * 64 + tx * 4);
        acc[0][0] = fmaf(a.x, b.x, acc[0][0]); acc[0][1] = fmaf(a.x, b.y, acc[0][1]);
        acc[0][2] = fmaf(a.x, b.z, acc[0][2]); acc[0][3] = fmaf(a.x, b.w, acc[0][3]);
        acc[1][0] = fmaf(a.y, b.x, acc[1][0]); acc[1][1] = fmaf(a.y, b.y, acc[1][1]);
        acc[1][2] = fmaf(a.y, b.z, acc[1][2]); acc[1][3] = fmaf(a.y, b.w, acc[1][3]);
        acc[2][0] = fmaf(a.z, b.x, acc[2][0]); acc[2][1] = fmaf(a.z, b.y, acc[2][1]);
        acc[2][2] = fmaf(a.z, b.z, acc[2][2]); acc[2][3] = fmaf(a.z, b.w, acc[2][3]);
        acc[3][0] = fmaf(a.w, b.x, acc[3][0]); acc[3][1] = fmaf(a.w, b.y, acc[3][1]);
        acc[3][2] = fmaf(a.w, b.z, acc[3][2]); acc[3][3] = fmaf(a.w, b.w, acc[3][3]);
    }

    float4 bia = make_float4(0.f, 0.f, 0.f, 0.f);
    if (bias) bia = *(const float4*)(bias + tx * 4);
    float4 asv = make_float4(0.f, 0.f, 0.f, 0.f), adv = asv;
    if (a_s) { asv = *(const float4*)(a_s + tx * 4); adv = *(const float4*)(a_d + tx * 4); }

    #pragma unroll
    for (int i = 0; i < 4; i++) {
        const int r = r0 + ty * 4 + i;
        if (r >= NN) break;
        float4 v = make_float4(acc[i][0] + bia.x, acc[i][1] + bia.y,
                               acc[i][2] + bia.z, acc[i][3] + bia.w);
        if (do_relu) {
            v.x = fmaxf(v.x, 0.f); v.y = fmaxf(v.y, 0.f);
            v.z = fmaxf(v.z, 0.f); v.w = fmaxf(v.w, 0.f);
        }
        if (out) {
            *(float4*)(out + r * 64 + tx * 4) = v;
        } else {
            const __half2 p0 = __floats2half2_rn(v.x, v.y);
            const __half2 p1 = __floats2half2_rn(v.z, v.w);
            uint2 pk;
            pk.x = *(const unsigned int*)&p0;
            pk.y = *(const unsigned int*)&p1;
            *(uint2*)(g_hxh + r * 64 + tx * 4) = pk;
        }
        if (a_s) {
            float vs = v.x * asv.x + v.y * asv.y + v.z * asv.z + v.w * asv.w;
            float vd = v.x * adv.x + v.y * adv.y + v.z * adv.z + v.w * adv.w;
            #pragma unroll
            for (int o = 8; o > 0; o >>= 1) {
                vs += __shfl_down_sync(0xffffffffu, vs, o, 16);
                vd += __shfl_down_sync(0xffffffffu, vd, o, 16);
            }
            if (tx == 0) { g_ssrc[r] = vs; g_sdst[r] = vd; }
        }
    }
}

// ---------------- fused GAT aggregate: one warp per dst node ----------------
// Single pass: softmax is shift-invariant, so no max-stabilization pass —
// exp-sum + fp16 gather merged, quarter-warp edge parallelism
// (8 lanes x 16B = one 128B row; 4 edges in flight per warp).
__global__ void __launch_bounds__(256) k_gat(float* __restrict__ out,
                                             const float* __restrict__ bias) {
    const int warp = threadIdx.x >> 5;
    const int lane = threadIdx.x & 31;
    const int node = blockIdx.x * 8 + warp;
    if (node >= NN) return;

    const int base = g_rowptr[node];
    const int end  = g_rowptr[node + 1];
    const float sdi = g_sdst[node];

    const int quarter = lane >> 3;   // 0..3: which edge of the group of 4
    const int sub     = lane & 7;    // owns cols sub*8 .. sub*8+7
    float f[8];
    #pragma unroll
    for (int i = 0; i < 8; i++) f[i] = 0.f;
    float esum = 0.f;

    #pragma unroll 2
    for (int j = base + quarter; j < end; j += 4) {
        const int s = g_csr_src[j];
        float a = g_ssrc[s] + sdi;
        a = (a >= 0.f) ? a : 0.2f * a;
        const float e = __expf(a);
        const uint4 raw = *(const uint4*)(g_hxh + s * 64 + sub * 8);
        const __half2* hp = (const __half2*)&raw;
        const float2 f0 = __half22float2(hp[0]);
        const float2 f1 = __half22float2(hp[1]);
        const float2 f2 = __half22float2(hp[2]);
        const float2 f3 = __half22float2(hp[3]);
        f[0] = fmaf(e, f0.x, f[0]); f[1] = fmaf(e, f0.y, f[1]);
        f[2] = fmaf(e, f1.x, f[2]); f[3] = fmaf(e, f1.y, f[3]);
        f[4] = fmaf(e, f2.x, f[4]); f[5] = fmaf(e, f2.y, f[5]);
        f[6] = fmaf(e, f3.x, f[6]); f[7] = fmaf(e, f3.y, f[7]);
        esum += e;
    }
    // combine the four quarters
    #pragma unroll
    for (int o = 8; o <= 16; o <<= 1) {
        esum += __shfl_xor_sync(0xffffffffu, esum, o);
        #pragma unroll
        for (int i = 0; i < 8; i++)
            f[i] += __shfl_xor_sync(0xffffffffu, f[i], o);
    }

    const float inv = (end > base) ? (1.0f / esum) : 0.0f;

    if (quarter == 0) {
        float4 ob0 = *(float4*)(out + node * 64 + sub * 8);
        float4 ob1 = *(float4*)(out + node * 64 + sub * 8 + 4);
        const float4 bb0 = *(const float4*)(bias + sub * 8);
        const float4 bb1 = *(const float4*)(bias + sub * 8 + 4);
        ob0.x += fmaxf(fmaf(f[0], inv, bb0.x), 0.f);
        ob0.y += fmaxf(fmaf(f[1], inv, bb0.y), 0.f);
        ob0.z += fmaxf(fmaf(f[2], inv, bb0.z), 0.f);
        ob0.w += fmaxf(fmaf(f[3], inv, bb0.w), 0.f);
        ob1.x += fmaxf(fmaf(f[4], inv, bb1.x), 0.f);
        ob1.y += fmaxf(fmaf(f[5], inv, bb1.y), 0.f);
        ob1.z += fmaxf(fmaf(f[6], inv, bb1.z), 0.f);
        ob1.w += fmaxf(fmaf(f[7], inv, bb1.w), 0.f);
        *(float4*)(out + node * 64 + sub * 8)     = ob0;
        *(float4*)(out + node * 64 + sub * 8 + 4) = ob1;
    }
}

// ---------------- launch ----------------
extern "C" void kernel_launch(void* const* d_in, const int* in_sizes, int n_in,
                              void* d_out, int out_size) {
    const float* x   = (const float*)d_in[0];
    const int*   ei  = (const int*)d_in[1];
    const float* W0  = (const float*)d_in[4];
    const float* b0  = (const float*)d_in[5];
    const float* W1  = (const float*)d_in[6];
    const float* as1 = (const float*)d_in[7];
    const float* ad1 = (const float*)d_in[8];
    const float* b1  = (const float*)d_in[9];
    const float* W2  = (const float*)d_in[10];
    const float* as2 = (const float*)d_in[11];
    const float* ad2 = (const float*)d_in[12];
    const float* b2  = (const float*)d_in[13];
    float* out = (float*)d_out;

    const int edgeBlocks = (EE + 255) / 256;
    const int gemmBlocks = (NN + 63) / 64;
    const int gatBlocks  = (NN + 7) / 8;

    k_detect_zero<<<(NN + 255) / 256, 256>>>(ei);
    k_hist<<<edgeBlocks, 256>>>(ei);
    k_scansum<<<SCAN_BLOCKS, 256>>>();
    k_scanout<<<SCAN_BLOCKS, 256>>>();
    k_fill<<<edgeBlocks, 256>>>(ei);

    // layer 0: out = relu(x @ W0 + b0)
    k_gemm<<<gemmBlocks, 256>>>(x, W0, b0, 1, nullptr, nullptr, out);

    // GAT layer 1
    k_gemm<<<gemmBlocks, 256>>>(out, W1, nullptr, 0, as1, ad1, nullptr);
    k_gat<<<gatBlocks, 256>>>(out, b1);

    // GAT layer 2
    k_gemm<<<gemmBlocks, 256>>>(out, W2, nullptr, 0, as2, ad2, nullptr);
    k_gat<<<gatBlocks, 256>>>(out, b2);
}

// round 10
// speedup vs baseline: 4.2704x; 1.1843x over previous
#include <cuda_runtime.h>
#include <cuda_fp16.h>

#define NN 50000
#define EE 800000
#define DD 64
#define SCAN_BLOCKS 49   // ceil(NN / 1024)

// ---------------- scratch (static device globals; no allocation) ----------------
__device__ __align__(16) int    g_csr_src[EE];     // src ids grouped by dst
__device__ __align__(16) __half g_hxh[NN * DD];    // fp16 feature matrix (gather source)
__device__ __align__(16) float  g_ssrc[NN];
__device__ __align__(16) float  g_sdst[NN];
__device__ __align__(16) int    g_deg[NN];         // zero at entry (init + re-zeroed each launch)
__device__ __align__(16) int    g_rowptr[NN + 4];
__device__ __align__(16) int    g_cursor[NN];
__device__ __align__(16) int    g_bsum[64];

// ---------------- helpers ----------------

// per-block int64-vs-int32 layout detection: int64 indices (< 2^31) have zero
// high words at odd int32 positions; random int32 data makes 64 consecutive
// zeros essentially impossible.
__device__ __forceinline__ int block_is64(const int* __restrict__ ei) {
    __shared__ int s_is64;
    if (threadIdx.x < 32) {
        int nz = ei[2 * threadIdx.x + 1] | ei[2 * (threadIdx.x + 32) + 1];
        unsigned m = __ballot_sync(0xffffffffu, nz != 0);
        if (threadIdx.x == 0) s_is64 = (m == 0);
    }
    __syncthreads();
    return s_is64;
}

__device__ __forceinline__ int load_dst(const int* __restrict__ ei, int e, int is64) {
    int d = is64 ? ei[2 * (EE + e)] : ei[EE + e];
    return min(max(d, 0), NN - 1);
}
__device__ __forceinline__ int load_src(const int* __restrict__ ei, int e, int is64) {
    int s = is64 ? ei[2 * e] : ei[e];
    return min(max(s, 0), NN - 1);
}

// ---------------- CSR build ----------------

// histogram of dst (g_deg is zero at entry)
__global__ void k_hist(const int* __restrict__ ei) {
    const int is64 = block_is64(ei);
    int e = blockIdx.x * blockDim.x + threadIdx.x;
    if (e < EE) atomicAdd(&g_deg[load_dst(ei, e, is64)], 1);
}

// scan pass 1: per-1024-chunk sums
__global__ void __launch_bounds__(256) k_scansum() {
    const int tid = threadIdx.x;
    const int lane = tid & 31, warp = tid >> 5;
    const int base = blockIdx.x * 1024 + tid * 4;
    int s = 0;
    if (base + 3 < NN) {
        const int4 v = *(const int4*)(g_deg + base);
        s = v.x + v.y + v.z + v.w;
    } else {
        #pragma unroll
        for (int i = 0; i < 4; i++) if (base + i < NN) s += g_deg[base + i];
    }
    #pragma unroll
    for (int o = 16; o > 0; o >>= 1) s += __shfl_xor_sync(0xffffffffu, s, o);
    __shared__ int ws[8];
    if (lane == 0) ws[warp] = s;
    __syncthreads();
    if (tid == 0) {
        int t = 0;
        #pragma unroll
        for (int i = 0; i < 8; i++) t += ws[i];
        g_bsum[blockIdx.x] = t;
    }
}

// scan pass 2: block offset from g_bsum, chunk scan -> rowptr/cursor; re-zero g_deg
__global__ void __launch_bounds__(256) k_scanout() {
    const int tid = threadIdx.x;
    const int lane = tid & 31, warp = tid >> 5;
    const int base = blockIdx.x * 1024 + tid * 4;

    __shared__ int s_boff;
    if (warp == 0) {
        int v = 0;
        if (lane < blockIdx.x) v = g_bsum[lane];
        if (lane + 32 < blockIdx.x) v += g_bsum[lane + 32];
        #pragma unroll
        for (int o = 16; o > 0; o >>= 1) v += __shfl_xor_sync(0xffffffffu, v, o);
        if (lane == 0) s_boff = v;
    }

    int4 v = make_int4(0, 0, 0, 0);
    if (base + 3 < NN) {
        v = *(const int4*)(g_deg + base);
        *(int4*)(g_deg + base) = make_int4(0, 0, 0, 0);   // leave zeroed for next launch
    } else {
        if (base + 0 < NN) { v.x = g_deg[base + 0]; g_deg[base + 0] = 0; }
        if (base + 1 < NN) { v.y = g_deg[base + 1]; g_deg[base + 1] = 0; }
        if (base + 2 < NN) { v.z = g_deg[base + 2]; g_deg[base + 2] = 0; }
        if (base + 3 < NN) { v.w = g_deg[base + 3]; g_deg[base + 3] = 0; }
    }
    const int s0 = v.x, s1 = s0 + v.y, s2 = s1 + v.z, s3 = s2 + v.w;
    const int tot = s3;

    int inc = tot;
    #pragma unroll
    for (int d = 1; d < 32; d <<= 1) {
        int a = __shfl_up_sync(0xffffffffu, inc, d);
        if (lane >= d) inc += a;
    }
    __shared__ int wtot[8];
    if (lane == 31) wtot[warp] = inc;
    __syncthreads();
    int woff = 0;
    for (int i = 0; i < warp; i++) woff += wtot[i];

    const int off = s_boff + woff + (inc - tot);
    const int4 rp = make_int4(off, off + s0, off + s1, off + s2);
    if (base + 3 < NN) {
        *(int4*)(g_rowptr + base) = rp;
        *(int4*)(g_cursor + base) = rp;
    } else {
        if (base + 0 < NN) { g_rowptr[base + 0] = rp.x; g_cursor[base + 0] = rp.x; }
        if (base + 1 < NN) { g_rowptr[base + 1] = rp.y; g_cursor[base + 1] = rp.y; }
        if (base + 2 < NN) { g_rowptr[base + 2] = rp.z; g_cursor[base + 2] = rp.z; }
        if (base + 3 < NN) { g_rowptr[base + 3] = rp.w; g_cursor[base + 3] = rp.w; }
    }
    if (blockIdx.x == 0 && tid == 0) g_rowptr[NN] = EE;
}

__global__ void k_fill(const int* __restrict__ ei) {
    const int is64 = block_is64(ei);
    int e = blockIdx.x * blockDim.x + threadIdx.x;
    if (e < EE) {
        const int d = load_dst(ei, e, is64);
        const int s = load_src(ei, e, is64);
        int pos = atomicAdd(&g_cursor[d], 1);
        g_csr_src[pos] = s;
    }
}

// ---------------- tensor-core GEMM: 128-row tile, 8 warps, m16n8k16 ----------------
// hx = h @ W (+bias,+relu optional). out!=null: fp32 to out.
// out==null: fp16 to g_hxh + attention dots to g_ssrc/g_sdst.
__global__ void __launch_bounds__(256) k_gemm_tc(
        const float* __restrict__ h, const float* __restrict__ W,
        const float* __restrict__ bias, int do_relu,
        const float* __restrict__ a_s, const float* __restrict__ a_d,
        float* __restrict__ out) {
    __shared__ __half sA[128 * 72];    // A tile fp16, pitch 72 (conflict-free)
    __shared__ __half sWt[64 * 72];    // W transposed: sWt[n][k]

    const int tid = threadIdx.x;
    const int warp = tid >> 5, lane = tid & 31;
    const int g = lane >> 2, tg = lane & 3;
    const int r0blk = blockIdx.x * 128;

    // W[k][n] fp32 -> sWt[n][k] fp16
    for (int idx = tid; idx < 4096; idx += 256) {
        const int k = idx >> 6, n = idx & 63;
        sWt[n * 72 + k] = __float2half_rn(W[idx]);
    }
    // A tile rows r0blk..+127 fp32 -> fp16
    {
        const int row = tid >> 1;
        const int c0 = (tid & 1) * 32;
        const int r = r0blk + row;
        if (r < NN) {
            const float4* src = (const float4*)(h + r * 64 + c0);
            #pragma unroll
            for (int i = 0; i < 8; i++) {
                const float4 v = src[i];
                *(__half2*)(sA + row * 72 + c0 + i * 4)     = __floats2half2_rn(v.x, v.y);
                *(__half2*)(sA + row * 72 + c0 + i * 4 + 2) = __floats2half2_rn(v.z, v.w);
            }
        } else {
            const __half2 z = __half2half2(__float2half(0.f));
            #pragma unroll
            for (int i = 0; i < 16; i++)
                *(__half2*)(sA + row * 72 + c0 + i * 2) = z;
        }
    }
    __syncthreads();

    const int rw = warp * 16;
    float acc[8][4];
    #pragma unroll
    for (int i = 0; i < 8; i++)
        #pragma unroll
        for (int j = 0; j < 4; j++) acc[i][j] = 0.f;

    #pragma unroll
    for (int k0 = 0; k0 < 64; k0 += 16) {
        const unsigned a0 = *(const unsigned*)(sA + (rw + g)     * 72 + k0 + 2 * tg);
        const unsigned a1 = *(const unsigned*)(sA + (rw + g + 8) * 72 + k0 + 2 * tg);
        const unsigned a2 = *(const unsigned*)(sA + (rw + g)     * 72 + k0 + 8 + 2 * tg);
        const unsigned a3 = *(const unsigned*)(sA + (rw + g + 8) * 72 + k0 + 8 + 2 * tg);
        #pragma unroll
        for (int i = 0; i < 8; i++) {
            const int n0 = i * 8;
            const unsigned b0 = *(const unsigned*)(sWt + (n0 + g) * 72 + k0 + 2 * tg);
            const unsigned b1 = *(const unsigned*)(sWt + (n0 + g) * 72 + k0 + 8 + 2 * tg);
            asm volatile(
                "mma.sync.aligned.m16n8k16.row.col.f32.f16.f16.f32 "
                "{%0,%1,%2,%3}, {%4,%5,%6,%7}, {%8,%9}, {%0,%1,%2,%3};"
                : "+f"(acc[i][0]), "+f"(acc[i][1]), "+f"(acc[i][2]), "+f"(acc[i][3])
                : "r"(a0), "r"(a1), "r"(a2), "r"(a3), "r"(b0), "r"(b1));
        }
    }

    // epilogue: thread holds rows {rA, rB}, cols {2tg,2tg+1} of each 8-col chunk
    const int rA = r0blk + rw + g;
    const int rB = rA + 8;
    float vsA = 0.f, vdA = 0.f, vsB = 0.f, vdB = 0.f;

    #pragma unroll
    for (int i = 0; i < 8; i++) {
        const int c = i * 8 + 2 * tg;
        float bx = 0.f, by = 0.f;
        if (bias) { bx = bias[c]; by = bias[c + 1]; }
        float v0 = acc[i][0] + bx, v1 = acc[i][1] + by;
        float v2 = acc[i][2] + bx, v3 = acc[i][3] + by;
        if (do_relu) {
            v0 = fmaxf(v0, 0.f); v1 = fmaxf(v1, 0.f);
            v2 = fmaxf(v2, 0.f); v3 = fmaxf(v3, 0.f);
        }
        if (out) {
            if (rA < NN) { float2 p = make_float2(v0, v1); *(float2*)(out + rA * 64 + c) = p; }
            if (rB < NN) { float2 p = make_float2(v2, v3); *(float2*)(out + rB * 64 + c) = p; }
        } else {
            if (rA < NN) *(__half2*)(g_hxh + rA * 64 + c) = __floats2half2_rn(v0, v1);
            if (rB < NN) *(__half2*)(g_hxh + rB * 64 + c) = __floats2half2_rn(v2, v3);
        }
        if (a_s) {
            const float as0 = a_s[c], as1 = a_s[c + 1];
            const float ad0 = a_d[c], ad1 = a_d[c + 1];
            vsA += v0 * as0 + v1 * as1; vdA += v0 * ad0 + v1 * ad1;
            vsB += v2 * as0 + v3 * as1; vdB += v2 * ad0 + v3 * ad1;
        }
    }
    if (a_s) {
        #pragma unroll
        for (int o = 2; o > 0; o >>= 1) {
            vsA += __shfl_down_sync(0xffffffffu, vsA, o, 4);
            vdA += __shfl_down_sync(0xffffffffu, vdA, o, 4);
            vsB += __shfl_down_sync(0xffffffffu, vsB, o, 4);
            vdB += __shfl_down_sync(0xffffffffu, vdB, o, 4);
        }
        if (tg == 0) {
            if (rA < NN) { g_ssrc[rA] = vsA; g_sdst[rA] = vdA; }
            if (rB < NN) { g_ssrc[rB] = vsB; g_sdst[rB] = vdB; }
        }
    }
}

// ---------------- fused GAT aggregate: one warp per dst node ----------------
__global__ void __launch_bounds__(256) k_gat(float* __restrict__ out,
                                             const float* __restrict__ bias) {
    const int warp = threadIdx.x >> 5;
    const int lane = threadIdx.x & 31;
    const int node = blockIdx.x * 8 + warp;
    if (node >= NN) return;

    const int base = g_rowptr[node];
    const int end  = g_rowptr[node + 1];
    const float sdi = g_sdst[node];

    const int quarter = lane >> 3;
    const int sub     = lane & 7;
    float f[8];
    #pragma unroll
    for (int i = 0; i < 8; i++) f[i] = 0.f;
    float esum = 0.f;

    #pragma unroll 2
    for (int j = base + quarter; j < end; j += 4) {
        const int s = g_csr_src[j];
        float a = g_ssrc[s] + sdi;
        a = (a >= 0.f) ? a : 0.2f * a;
        const float e = __expf(a);
        const uint4 raw = *(const uint4*)(g_hxh + s * 64 + sub * 8);
        const __half2* hp = (const __half2*)&raw;
        const float2 f0 = __half22float2(hp[0]);
        const float2 f1 = __half22float2(hp[1]);
        const float2 f2 = __half22float2(hp[2]);
        const float2 f3 = __half22float2(hp[3]);
        f[0] = fmaf(e, f0.x, f[0]); f[1] = fmaf(e, f0.y, f[1]);
        f[2] = fmaf(e, f1.x, f[2]); f[3] = fmaf(e, f1.y, f[3]);
        f[4] = fmaf(e, f2.x, f[4]); f[5] = fmaf(e, f2.y, f[5]);
        f[6] = fmaf(e, f3.x, f[6]); f[7] = fmaf(e, f3.y, f[7]);
        esum += e;
    }
    #pragma unroll
    for (int o = 8; o <= 16; o <<= 1) {
        esum += __shfl_xor_sync(0xffffffffu, esum, o);
        #pragma unroll
        for (int i = 0; i < 8; i++)
            f[i] += __shfl_xor_sync(0xffffffffu, f[i], o);
    }

    const float inv = (end > base) ? (1.0f / esum) : 0.0f;

    if (quarter == 0) {
        float4 ob0 = *(float4*)(out + node * 64 + sub * 8);
        float4 ob1 = *(float4*)(out + node * 64 + sub * 8 + 4);
        const float4 bb0 = *(const float4*)(bias + sub * 8);
        const float4 bb1 = *(const float4*)(bias + sub * 8 + 4);
        ob0.x += fmaxf(fmaf(f[0], inv, bb0.x), 0.f);
        ob0.y += fmaxf(fmaf(f[1], inv, bb0.y), 0.f);
        ob0.z += fmaxf(fmaf(f[2], inv, bb0.z), 0.f);
        ob0.w += fmaxf(fmaf(f[3], inv, bb0.w), 0.f);
        ob1.x += fmaxf(fmaf(f[4], inv, bb1.x), 0.f);
        ob1.y += fmaxf(fmaf(f[5], inv, bb1.y), 0.f);
        ob1.z += fmaxf(fmaf(f[6], inv, bb1.z), 0.f);
        ob1.w += fmaxf(fmaf(f[7], inv, bb1.w), 0.f);
        *(float4*)(out + node * 64 + sub * 8)     = ob0;
        *(float4*)(out + node * 64 + sub * 8 + 4) = ob1;
    }
}

// ---------------- launch ----------------
extern "C" void kernel_launch(void* const* d_in, const int* in_sizes, int n_in,
                              void* d_out, int out_size) {
    const float* x   = (const float*)d_in[0];
    const int*   ei  = (const int*)d_in[1];
    const float* W0  = (const float*)d_in[4];
    const float* b0  = (const float*)d_in[5];
    const float* W1  = (const float*)d_in[6];
    const float* as1 = (const float*)d_in[7];
    const float* ad1 = (const float*)d_in[8];
    const float* b1  = (const float*)d_in[9];
    const float* W2  = (const float*)d_in[10];
    const float* as2 = (const float*)d_in[11];
    const float* ad2 = (const float*)d_in[12];
    const float* b2  = (const float*)d_in[13];
    float* out = (float*)d_out;

    const int edgeBlocks = (EE + 255) / 256;
    const int gemmBlocks = (NN + 127) / 128;
    const int gatBlocks  = (NN + 7) / 8;

    k_hist<<<edgeBlocks, 256>>>(ei);
    k_scansum<<<SCAN_BLOCKS, 256>>>();
    k_scanout<<<SCAN_BLOCKS, 256>>>();
    k_fill<<<edgeBlocks, 256>>>(ei);

    // layer 0: out = relu(x @ W0 + b0)
    k_gemm_tc<<<gemmBlocks, 256>>>(x, W0, b0, 1, nullptr, nullptr, out);

    // GAT layer 1
    k_gemm_tc<<<gemmBlocks, 256>>>(out, W1, nullptr, 0, as1, ad1, nullptr);
    k_gat<<<gatBlocks, 256>>>(out, b1);

    // GAT layer 2
    k_gemm_tc<<<gemmBlocks, 256>>>(out, W2, nullptr, 0, as2, ad2, nullptr);
    k_gat<<<gatBlocks, 256>>>(out, b2);
}